// round 14
// baseline (speedup 1.0000x reference)
#include <cuda_runtime.h>
#include <math.h>

#define B_SZ   32
#define CIN    2048
#define CR     256
#define NPOS   289            // 17*17
#define FEAT   32896          // 256*257/2
#define NSWEEPS 9
#define NPAIRS 128
#define NBLK   8128           // 128*127/2
#define EPS_CLIP 1e-4f
#define SQRT2F  1.41421356237309515f

// ------------------------- device scratch (static, no alloc) ---------------
__device__ float P_buf[(size_t)B_SZ * CIN * NPOS];   // pooled   [b][c][p]
__device__ float G_buf[(size_t)B_SZ * CR * NPOS];    // reduced  [b][d][p]
__device__ float A_buf[(size_t)B_SZ * FEAT];         // packed lower-tri cov
__device__ float V_buf[(size_t)B_SZ * CR * CR];      // V^T: [b][eigvec e][comp]
__device__ float WL_buf[B_SZ * CR];                  // log(clamped eigenvalues)
__device__ float F_buf[(size_t)B_SZ * FEAT];         // flattened logm features
__device__ float H_buf[B_SZ * 256];                  // hidden layer
__device__ float2 CSN_g[B_SZ * 128];                 // per-round angles (L2)

// per-round bank-sorted block tables (round- and sweep-invariant)
__device__ ushort4 SIdx[255 * NBLK];                 // packed-tri offsets, 16.6 MB
__device__ uchar2  SK[255 * NBLK];                   // (ka,kb) per block, 4.1 MB

// ------------------------- helpers -----------------------------------------
__device__ __forceinline__ int pidx(int i, int j) {
    int mx = i > j ? i : j;
    int mn = i > j ? j : i;
    return mx * (mx + 1) / 2 + mn;
}

// round-robin tournament pairing: round r in [0,255), pair k in [0,128)
__device__ __forceinline__ void get_pair(int r, int k, int& p, int& q) {
    if (k == 0) { p = r; q = 255; return; }
    int a = r + k;  if (a >= 255) a -= 255;
    int b = r - k;  if (b < 0)    b += 255;
    p = a < b ? a : b;
    q = a < b ? b : a;
}

__device__ __forceinline__ unsigned smem_u32(const void* p) {
    return (unsigned)__cvta_generic_to_shared(p);
}

#define MBAR_INIT(addr, cnt) \
    asm volatile("mbarrier.init.shared.b64 [%0], %1;" :: "r"(addr), "r"(cnt) : "memory")

// example-verified remote arrive: mapa + plain shared::cluster arrive
#define MBAR_ARRIVE_REMOTE(addr, rank) \
    asm volatile("{\n\t.reg .b32 ra;\n\t" \
                 "mapa.shared::cluster.u32 ra, %0, %1;\n\t" \
                 "mbarrier.arrive.shared::cluster.b64 _, [ra];\n\t}" \
                 :: "r"(addr), "r"(rank) : "memory")

// example-verified wait: acquire.cta try_wait spin
#define MBAR_WAIT(addr, parity) do {                                          \
    unsigned _m = (addr), _p = (parity);                                      \
    asm volatile(                                                             \
        "{\n\t.reg .pred P1;\n\t"                                             \
        "WL_%=:\n\t"                                                          \
        "mbarrier.try_wait.parity.acquire.cta.shared::cta.b64 P1, [%0], %1, 0x989680;\n\t" \
        "@P1 bra.uni WD_%=;\n\t"                                              \
        "bra.uni WL_%=;\n\t"                                                  \
        "WD_%=:\n\t}"                                                         \
        :: "r"(_m), "r"(_p) : "memory");                                      \
} while (0)

#define FENCE_CLUSTER() asm volatile("fence.acq_rel.cluster;" ::: "memory")
#define CLUSTER_SYNC() do {                                            \
    asm volatile("barrier.cluster.arrive.aligned;" ::: "memory");      \
    asm volatile("barrier.cluster.wait.aligned;"   ::: "memory");      \
} while (0)

// ------------------------- K0: per-round bank-sorted tables -----------------
// For each round r, emit the 8128 off-diagonal blocks so that consecutive
// groups of 32 table entries have distinct banks on ix.x (region 1,
// interleaved one-per-bucket); leftovers go to a contiguous region 2.
// Any block order is numerically identical (disjoint element sets), so the
// atomic-ordered bucket fill does not affect results.
__global__ void init_sorted() {        // grid 255, block 128
    __shared__ int hist[32], cur[32], cur2, sminS;
    int r = blockIdx.x, t = threadIdx.x;
    if (t < 32) hist[t] = 0;
    __syncthreads();
    if (t < 127) {
        int pa, qa; get_pair(r, t, pa, qa);
        for (int kb = t + 1; kb < 128; kb++) {
            int pb, qb; get_pair(r, kb, pb, qb);
            atomicAdd(&hist[pidx(pa, pb) & 31], 1);
        }
    }
    __syncthreads();
    if (t == 0) {
        int m = hist[0];
        for (int i = 1; i < 32; i++) m = min(m, hist[i]);
        sminS = m; cur2 = m * 32;
        for (int i = 0; i < 32; i++) cur[i] = 0;
    }
    __syncthreads();
    int s_min = sminS;
    size_t rbase = (size_t)r * NBLK;
    if (t < 127) {
        int ka = t;
        int pa, qa; get_pair(r, ka, pa, qa);
        for (int kb = ka + 1; kb < 128; kb++) {
            int pb, qb; get_pair(r, kb, pb, qb);
            int i00 = pidx(pa, pb);
            int bank = i00 & 31;
            int g = atomicAdd(&cur[bank], 1);
            int dest = (g < s_min) ? (g * 32 + bank) : atomicAdd(&cur2, 1);
            ushort4 v;
            v.x = (unsigned short)i00;
            v.y = (unsigned short)pidx(pa, qb);
            v.z = (unsigned short)pidx(qa, pb);
            v.w = (unsigned short)pidx(qa, qb);
            SIdx[rbase + dest] = v;
            SK[rbase + dest] = make_uchar2((unsigned char)ka, (unsigned char)kb);
        }
    }
}

// ------------------------- K1: 2x2 average pool -----------------------------
__global__ void pool_kernel(const float* __restrict__ x) {
    size_t idx = (size_t)blockIdx.x * 256 + threadIdx.x;   // B*CIN*NPOS
    if (idx >= (size_t)B_SZ * CIN * NPOS) return;
    int p = (int)(idx % NPOS);
    size_t bc = idx / NPOS;
    int py = p / 17, px = p % 17;
    const float* base = x + bc * (34 * 34) + (py * 2) * 34 + px * 2;
    float2 r0 = *(const float2*)base;
    float2 r1 = *(const float2*)(base + 34);
    P_buf[idx] = (r0.x + r0.y + r1.x + r1.y) * 0.25f;
}

// ------------------------- K2: channel reduce GEMM --------------------------
// G[b][d][p] = sum_c W_red[d][c] * P[b][c][p]   (M=256, N=289, K=2048)
#define RK 16
__global__ void reduce_gemm_kernel(const float* __restrict__ W_red) {
    int b  = blockIdx.z;
    int dt = blockIdx.y * 64;
    int pt = blockIdx.x * 64;
    __shared__ float Ws[RK][68];
    __shared__ float Ps[RK][68];
    int tid = threadIdx.x;            // 256
    int ty = tid >> 4, tx = tid & 15; // 4x4 micro-tile
    float acc[4][4];
#pragma unroll
    for (int i = 0; i < 4; i++)
#pragma unroll
        for (int j = 0; j < 4; j++) acc[i][j] = 0.f;

    const float* Pb = P_buf + (size_t)b * CIN * NPOS;

    for (int k0 = 0; k0 < CIN; k0 += RK) {
#pragma unroll
        for (int u = 0; u < 4; u++) {
            int idx = tid + u * 256;
            int dd = idx >> 4, kk = idx & 15;
            Ws[kk][dd] = W_red[(size_t)(dt + dd) * CIN + k0 + kk];
        }
#pragma unroll
        for (int u = 0; u < 4; u++) {
            int idx = tid + u * 256;
            int kk = idx >> 6, pp = idx & 63;
            int p = pt + pp;
            Ps[kk][pp] = (p < NPOS) ? Pb[(size_t)(k0 + kk) * NPOS + p] : 0.f;
        }
        __syncthreads();
#pragma unroll
        for (int kk = 0; kk < RK; kk++) {
            float wv[4], pv[4];
#pragma unroll
            for (int i = 0; i < 4; i++) wv[i] = Ws[kk][ty * 4 + i];
#pragma unroll
            for (int j = 0; j < 4; j++) pv[j] = Ps[kk][tx * 4 + j];
#pragma unroll
            for (int i = 0; i < 4; i++)
#pragma unroll
                for (int j = 0; j < 4; j++)
                    acc[i][j] = fmaf(wv[i], pv[j], acc[i][j]);
        }
        __syncthreads();
    }
#pragma unroll
    for (int i = 0; i < 4; i++) {
        int d = dt + ty * 4 + i;
#pragma unroll
        for (int j = 0; j < 4; j++) {
            int p = pt + tx * 4 + j;
            if (p < NPOS)
                G_buf[((size_t)b * CR + d) * NPOS + p] = acc[i][j];
        }
    }
}

// ------------------------- K3a: mean over positions + center ---------------
__global__ void mean_center_kernel() {
    int row  = blockIdx.x * 8 + (threadIdx.x >> 5);   // (b*256 + d)
    int lane = threadIdx.x & 31;
    float* g = &G_buf[(size_t)row * NPOS];
    float sum = 0.f;
    for (int p = lane; p < NPOS; p += 32) sum += g[p];
#pragma unroll
    for (int o = 16; o; o >>= 1) sum += __shfl_xor_sync(0xFFFFFFFFu, sum, o);
    float m = sum * (1.0f / NPOS);
    for (int p = lane; p < NPOS; p += 32) g[p] -= m;
}

// ------------------------- K3b: covariance (packed lower triangle) ---------
__global__ void cov_kernel() {
    int b  = blockIdx.y;
    int tp = blockIdx.x;  // lower-tri 32x32 tile pair (it >= jt), 36 total
    int it = 0;
    { int t = tp; while ((it + 1) * (it + 2) / 2 <= t) it++; (void)t; }
    int jt = tp - it * (it + 1) / 2;

    __shared__ float SI[17][34];
    __shared__ float SJ[17][34];

    const float* Gi = G_buf + ((size_t)b * CR + it * 32) * NPOS;
    const float* Gj = G_buf + ((size_t)b * CR + jt * 32) * NPOS;

    int tid = threadIdx.x;
    int ii = (tid & 15) * 2, jj = (tid >> 4) * 2;
    float a00 = 0.f, a01 = 0.f, a10 = 0.f, a11 = 0.f;

    for (int pc = 0; pc < NPOS; pc += 17) {
#pragma unroll
        for (int u = 0; u < 3; u++) {
            int idx = tid + u * 256;
            if (idx < 544) {
                int r = idx / 17, pp = idx % 17;
                SI[pp][r] = Gi[(size_t)r * NPOS + pc + pp];
                SJ[pp][r] = Gj[(size_t)r * NPOS + pc + pp];
            }
        }
        __syncthreads();
#pragma unroll
        for (int pp = 0; pp < 17; pp++) {
            float x0 = SI[pp][ii], x1 = SI[pp][ii + 1];
            float y0 = SJ[pp][jj], y1 = SJ[pp][jj + 1];
            a00 = fmaf(x0, y0, a00); a01 = fmaf(x0, y1, a01);
            a10 = fmaf(x1, y0, a10); a11 = fmaf(x1, y1, a11);
        }
        __syncthreads();
    }
    const float inv = 1.0f / (NPOS - 1);
    float* Ap = A_buf + (size_t)b * FEAT;
    int gi = it * 32 + ii, gj = jt * 32 + jj;
    if (gi     >= gj    ) Ap[gi * (gi + 1) / 2 + gj]           = a00 * inv;
    if (gi     >= gj + 1) Ap[gi * (gi + 1) / 2 + gj + 1]       = a01 * inv;
    if (gi + 1 >= gj    ) Ap[(gi + 1) * (gi + 2) / 2 + gj]     = a10 * inv;
    if (gi + 1 >= gj + 1) Ap[(gi + 1) * (gi + 2) / 2 + gj + 1] = a11 * inv;
}

// ------------------------- K4: clustered parallel cyclic Jacobi -------------
// Cluster of 4 CTAs per matrix:
//   rank 0 : packed A in smem, angles + all 32 warps on 2x2 block updates
//   rank 1 : V^T components [0,128)   for ALL 256 eigvec rows (smem 128 KB)
//   rank 2 : V^T components [128,256)
//   rank 3 : idle, parks at the final cluster barrier
#define JSMEM (FEAT * 4 + 128 * 8)   // rank0: As+csn; rankV: Vh(131072B)+csn

__global__ __launch_bounds__(1024, 1) __cluster_dims__(4, 1, 1)
void jacobi_cluster_kernel() {
    extern __shared__ float smem[];
    float*  As  = smem;                       // rank0: FEAT; rankV: Vh[256][128]
    float2* csn = (float2*)(smem + FEAT);     // 128 (c,s)

    __shared__ __align__(8) unsigned long long go_bar;   // V-CTAs: rank0 arrives
    __shared__ __align__(8) unsigned long long ack_bar;  // rank0: V-CTAs arrive (cnt=2)

    int tid  = threadIdx.x;
    int warp = tid >> 5, lane = tid & 31;
    unsigned rank;
    asm("mov.u32 %0, %%cluster_ctarank;" : "=r"(rank));
    int b = blockIdx.x >> 2;
    float2* csn_g = CSN_g + b * 128;

    unsigned go_a  = smem_u32(&go_bar);
    unsigned ack_a = smem_u32(&ack_bar);

    // barrier init + initial population
    if (tid == 0) {
        if (rank == 0) MBAR_INIT(ack_a, 2);
        if (rank == 1 || rank == 2) MBAR_INIT(go_a, 1);
    }
    if (rank == 0) {
        for (int i = tid; i < FEAT; i += 1024)
            As[i] = A_buf[(size_t)b * FEAT + i];
    } else if (rank == 1 || rank == 2) {
        int c0 = (rank == 1) ? 0 : 128;
        for (int i = tid; i < 256 * 128; i += 1024) {
            int e = i >> 7, c = i & 127;
            As[i] = ((c0 + c) == e) ? 1.f : 0.f;   // V^T = I (column slab)
        }
    }
    __syncthreads();
    CLUSTER_SYNC();   // mbarrier inits visible before any remote arrive

    if (rank == 0) {
        // =================== rank 0: A-side Jacobi ===================
        int t_round = 0;
        for (int sw = 0; sw < NSWEEPS; sw++) {
            for (int r = 0; r < 255; r++, t_round++) {
                if (t_round > 0 && tid == 0)
                    MBAR_WAIT(ack_a, (t_round - 1) & 1);  // csn consumed
                __syncthreads();

                // ---- phase 1: angles + diagonal 2x2 of each pair ----
                if (tid < 128) {
                    int p, q; get_pair(r, tid, p, q);
                    int ipp = p * (p + 1) / 2 + p;
                    int iqq = q * (q + 1) / 2 + q;
                    int ipq = q * (q + 1) / 2 + p;
                    float app = As[ipp], aqq = As[iqq], apq = As[ipq];
                    float c = 1.f, s = 0.f;
                    if (fabsf(apq) > 1e-37f) {
                        float tau = (aqq - app) / (2.f * apq);
                        float t = copysignf(1.f, tau) /
                                  (fabsf(tau) + sqrtf(fmaf(tau, tau, 1.f)));
                        c = rsqrtf(fmaf(t, t, 1.f));
                        s = t * c;
                        As[ipp] = app - t * apq;
                        As[iqq] = aqq + t * apq;
                        As[ipq] = 0.f;
                    }
                    csn[tid] = make_float2(c, s);
                    __stcg(&csn_g[tid], make_float2(c, s));  // L2-coherent
                }
                __syncthreads();   // csn stores issued before signal
                if (tid == 0) {
                    FENCE_CLUSTER();               // release (cumulative)
                    MBAR_ARRIVE_REMOTE(go_a, 1);
                    MBAR_ARRIVE_REMOTE(go_a, 2);
                }

                // ---- phase 2: 8128 off-diagonal 2x2 blocks (smem) ----
                const ushort4* itab = SIdx + (size_t)r * NBLK;
                const uchar2*  ktab = SK   + (size_t)r * NBLK;
#pragma unroll 4
                for (int idx = tid; idx < NBLK; idx += 1024) {
                    ushort4 ix = itab[idx];       // coalesced LDG.64 (L2)
                    uchar2  kk = ktab[idx];
                    float2 ca = csn[kk.x];
                    float2 cb = csn[kk.y];
                    float b00 = As[ix.x], b01 = As[ix.y];
                    float b10 = As[ix.z], b11 = As[ix.w];
                    float r00 = ca.x * b00 - ca.y * b10;
                    float r01 = ca.x * b01 - ca.y * b11;
                    float r10 = ca.y * b00 + ca.x * b10;
                    float r11 = ca.y * b01 + ca.x * b11;
                    As[ix.x] = cb.x * r00 - cb.y * r01;
                    As[ix.y] = cb.y * r00 + cb.x * r01;
                    As[ix.z] = cb.x * r10 - cb.y * r11;
                    As[ix.w] = cb.y * r10 + cb.x * r11;
                }
                __syncthreads();
            }
        }
        if (tid < 256) {
            float wv = As[tid * (tid + 1) / 2 + tid];
            WL_buf[b * 256 + tid] = logf(fmaxf(wv, EPS_CLIP));
        }
    } else if (rank == 1 || rank == 2) {
        // ============ ranks 1,2: V^T row rotation on a column slab ==========
        int t_round = 0;
        for (int sw = 0; sw < NSWEEPS; sw++) {
            for (int r = 0; r < 255; r++, t_round++) {
                if (tid == 0) MBAR_WAIT(go_a, t_round & 1);
                __syncthreads();
                if (tid == 0) FENCE_CLUSTER();     // acquire side
                __syncthreads();
                if (tid < 128) csn[tid] = __ldcg(&csn_g[tid]);
                __syncthreads();

                // 128 pairs; warp handles one pair, lanes cover 32 float4 cols
#pragma unroll
                for (int pass = 0; pass < 4; pass++) {
                    int k = warp * 4 + pass;
                    float2 cv = csn[k];
                    int p, q; get_pair(r, k, p, q);
                    float4* vp = (float4*)(As + p * 128);
                    float4* vq = (float4*)(As + q * 128);
                    float4 a = vp[lane], d = vq[lane];
                    float4 np, nq;
                    np.x = cv.x * a.x - cv.y * d.x;  nq.x = cv.y * a.x + cv.x * d.x;
                    np.y = cv.x * a.y - cv.y * d.y;  nq.y = cv.y * a.y + cv.x * d.y;
                    np.z = cv.x * a.z - cv.y * d.z;  nq.z = cv.y * a.z + cv.x * d.z;
                    np.w = cv.x * a.w - cv.y * d.w;  nq.w = cv.y * a.w + cv.x * d.w;
                    vp[lane] = np; vq[lane] = nq;
                }
                __syncthreads();
                if (tid == 0) {
                    FENCE_CLUSTER();
                    MBAR_ARRIVE_REMOTE(ack_a, 0);
                }
            }
        }
        // write column slab back: V_buf[b][e][c0+c] = Vh[e][c]
        int c0 = (rank == 1) ? 0 : 128;
        for (int i = tid; i < 256 * 128; i += 1024) {
            int e = i >> 7, c = i & 127;
            V_buf[((size_t)b * CR + e) * CR + c0 + c] = As[i];
        }
    }
    // rank 3 falls through directly; ALL ranks park here before exit
    CLUSTER_SYNC();
}

// ------------------------- K5: logm reconstruct + triu flatten --------------
// F[b][t(i,j)] = scale(i,j) * sum_e wl[e] * V[e][i] * V[e][j]   (i <= j)
__global__ void recon_kernel() {
    int b  = blockIdx.y;
    int tp = blockIdx.x;  // upper-tri tile pairs ti <= tj among 8 -> 36
    int ti = 0;
    { int rem = tp; while (rem >= 8 - ti) { rem -= (8 - ti); ti++; } tp = rem; }
    int tj = ti + tp;

    __shared__ float SI[32][33];
    __shared__ float SJ[32][33];

    const float* Vb = V_buf + (size_t)b * CR * CR;
    const float* wl = WL_buf + b * 256;
    int tid = threadIdx.x;
    int ii = (tid & 15) * 2, jj = (tid >> 4) * 2;
    float a00 = 0.f, a01 = 0.f, a10 = 0.f, a11 = 0.f;

    for (int ec = 0; ec < 256; ec += 32) {
#pragma unroll
        for (int u = 0; u < 4; u++) {
            int idx = tid + u * 256;
            int ee = idx >> 5, c = idx & 31;
            float wv = wl[ec + ee];
            SI[ee][c] = Vb[(size_t)(ec + ee) * CR + ti * 32 + c];
            SJ[ee][c] = wv * Vb[(size_t)(ec + ee) * CR + tj * 32 + c];
        }
        __syncthreads();
#pragma unroll
        for (int ee = 0; ee < 32; ee++) {
            float x0 = SI[ee][ii], x1 = SI[ee][ii + 1];
            float y0 = SJ[ee][jj], y1 = SJ[ee][jj + 1];
            a00 = fmaf(x0, y0, a00); a01 = fmaf(x0, y1, a01);
            a10 = fmaf(x1, y0, a10); a11 = fmaf(x1, y1, a11);
        }
        __syncthreads();
    }

    float* Fb = F_buf + (size_t)b * FEAT;
    int gi = ti * 32 + ii, gj = tj * 32 + jj;
#pragma unroll
    for (int di = 0; di < 2; di++)
#pragma unroll
        for (int dj = 0; dj < 2; dj++) {
            int i = gi + di, j = gj + dj;
            if (i <= j) {
                float v = (di == 0) ? (dj == 0 ? a00 : a01)
                                    : (dj == 0 ? a10 : a11);
                int t = i * 256 - i * (i - 1) / 2 + (j - i);
                Fb[t] = v * (i == j ? 1.f : SQRT2F);
            }
        }
}

// ------------------------- K6: MLP layer 1 (float4) -------------------------
__global__ void mlp1_kernel(const float* __restrict__ W1,
                            const float* __restrict__ b1) {
    int k  = blockIdx.x;          // 0..255
    int bg = blockIdx.y * 8;      // batch group of 8
    int tid = threadIdx.x;        // 256
    const float4* wrow = (const float4*)(W1 + (size_t)k * FEAT);
    const int F4 = FEAT / 4;      // 8224
    float acc[8];
#pragma unroll
    for (int u = 0; u < 8; u++) acc[u] = 0.f;

    for (int t = tid; t < F4; t += 256) {
        float4 w = wrow[t];
#pragma unroll
        for (int u = 0; u < 8; u++) {
            float4 f = ((const float4*)(F_buf + (size_t)(bg + u) * FEAT))[t];
            acc[u] = fmaf(w.x, f.x, fmaf(w.y, f.y,
                     fmaf(w.z, f.z, fmaf(w.w, f.w, acc[u]))));
        }
    }
#pragma unroll
    for (int u = 0; u < 8; u++)
#pragma unroll
        for (int o = 16; o; o >>= 1)
            acc[u] += __shfl_xor_sync(0xFFFFFFFFu, acc[u], o);

    __shared__ float part[8][8];
    if ((tid & 31) == 0) {
#pragma unroll
        for (int u = 0; u < 8; u++) part[u][tid >> 5] = acc[u];
    }
    __syncthreads();
    if (tid < 8) {
        float s = 0.f;
#pragma unroll
        for (int w = 0; w < 8; w++) s += part[tid][w];
        s += b1[k];
        H_buf[(bg + tid) * 256 + k] = fmaxf(s, 0.f);
    }
}

// ------------------------- K7: MLP layer 2 ----------------------------------
__global__ void mlp2_kernel(const float* __restrict__ W2,
                            const float* __restrict__ b2,
                            float* __restrict__ out) {
    int b = blockIdx.x;
    int warp = threadIdx.x >> 5, lane = threadIdx.x & 31;
    if (warp < 3) {
        float s = 0.f;
        for (int k = lane; k < 256; k += 32)
            s = fmaf(H_buf[b * 256 + k], W2[warp * 256 + k], s);
#pragma unroll
        for (int o = 16; o; o >>= 1) s += __shfl_xor_sync(0xFFFFFFFFu, s, o);
        if (lane == 0) out[b * 3 + warp] = s + b2[warp];
    }
}

// ------------------------- launcher -----------------------------------------
extern "C" void kernel_launch(void* const* d_in, const int* in_sizes, int n_in,
                              void* d_out, int out_size) {
    const float* x     = (const float*)d_in[0];
    const float* W_red = (const float*)d_in[1];
    const float* W1    = (const float*)d_in[2];
    const float* b1    = (const float*)d_in[3];
    const float* W2    = (const float*)d_in[4];
    const float* b2    = (const float*)d_in[5];
    float* out = (float*)d_out;

    cudaFuncSetAttribute(jacobi_cluster_kernel,
                         cudaFuncAttributeMaxDynamicSharedMemorySize, JSMEM);

    init_sorted<<<255, 128>>>();
    pool_kernel<<<(B_SZ * CIN * NPOS) / 256, 256>>>(x);
    reduce_gemm_kernel<<<dim3(5, 4, B_SZ), 256>>>(W_red);
    mean_center_kernel<<<(B_SZ * CR) / 8, 256>>>();
    cov_kernel<<<dim3(36, B_SZ), 256>>>();
    jacobi_cluster_kernel<<<B_SZ * 4, 1024, JSMEM>>>();
    recon_kernel<<<dim3(36, B_SZ), 256>>>();
    mlp1_kernel<<<dim3(256, 4), 256>>>(W1, b1);
    mlp2_kernel<<<B_SZ, 128>>>(W2, b2, out);
}

// round 15
// speedup vs baseline: 1.4023x; 1.4023x over previous
#include <cuda_runtime.h>
#include <math.h>

#define B_SZ   32
#define CIN    2048
#define CR     256
#define NPOS   289            // 17*17
#define FEAT   32896          // 256*257/2
#define NSWEEPS 9
#define NPAIRS 128
#define NBLK   8128           // 128*127/2
#define EPS_CLIP 1e-4f
#define SQRT2F  1.41421356237309515f

// ------------------------- device scratch (static, no alloc) ---------------
__device__ float P_buf[(size_t)B_SZ * CIN * NPOS];   // pooled   [b][c][p]
__device__ float G_buf[(size_t)B_SZ * CR * NPOS];    // reduced  [b][d][p]
__device__ float A_buf[(size_t)B_SZ * FEAT];         // packed lower-tri cov
__device__ float V_buf[(size_t)B_SZ * CR * CR];      // V^T: [b][eigvec e][comp]
__device__ float WL_buf[B_SZ * CR];                  // log(clamped eigenvalues)
__device__ float F_buf[(size_t)B_SZ * FEAT];         // flattened logm features
__device__ float H_buf[B_SZ * 256];                  // hidden layer
__device__ float2 CSN_g[B_SZ * 128];                 // per-round angles (L2)

// precomputed Jacobi index tables (round- and sweep-invariant), natural order:
// consecutive entries share ka (broadcast csn loads) with ascending kb.
__device__ ushort4 IdxTab[255 * NBLK];               // 16.6 MB, L2-resident
__device__ uchar2  KTab[NBLK];                       // (ka,kb) per block

// ------------------------- helpers -----------------------------------------
__device__ __forceinline__ int pidx(int i, int j) {
    int mx = i > j ? i : j;
    int mn = i > j ? j : i;
    return mx * (mx + 1) / 2 + mn;
}

// round-robin tournament pairing: round r in [0,255), pair k in [0,128)
__device__ __forceinline__ void get_pair(int r, int k, int& p, int& q) {
    if (k == 0) { p = r; q = 255; return; }
    int a = r + k;  if (a >= 255) a -= 255;
    int b = r - k;  if (b < 0)    b += 255;
    p = a < b ? a : b;
    q = a < b ? b : a;
}

__device__ __forceinline__ unsigned smem_u32(const void* p) {
    return (unsigned)__cvta_generic_to_shared(p);
}

#define MBAR_INIT(addr, cnt) \
    asm volatile("mbarrier.init.shared.b64 [%0], %1;" :: "r"(addr), "r"(cnt) : "memory")

// example-verified remote arrive: mapa + plain shared::cluster arrive
#define MBAR_ARRIVE_REMOTE(addr, rank) \
    asm volatile("{\n\t.reg .b32 ra;\n\t" \
                 "mapa.shared::cluster.u32 ra, %0, %1;\n\t" \
                 "mbarrier.arrive.shared::cluster.b64 _, [ra];\n\t}" \
                 :: "r"(addr), "r"(rank) : "memory")

// example-verified wait: acquire.cta try_wait spin
#define MBAR_WAIT(addr, parity) do {                                          \
    unsigned _m = (addr), _p = (parity);                                      \
    asm volatile(                                                             \
        "{\n\t.reg .pred P1;\n\t"                                             \
        "WL_%=:\n\t"                                                          \
        "mbarrier.try_wait.parity.acquire.cta.shared::cta.b64 P1, [%0], %1, 0x989680;\n\t" \
        "@P1 bra.uni WD_%=;\n\t"                                              \
        "bra.uni WL_%=;\n\t"                                                  \
        "WD_%=:\n\t}"                                                         \
        :: "r"(_m), "r"(_p) : "memory");                                      \
} while (0)

#define FENCE_CLUSTER() asm volatile("fence.acq_rel.cluster;" ::: "memory")
#define CLUSTER_SYNC() do {                                            \
    asm volatile("barrier.cluster.arrive.aligned;" ::: "memory");      \
    asm volatile("barrier.cluster.wait.aligned;"   ::: "memory");      \
} while (0)

// ------------------------- K0a: (ka<kb) enumeration -------------------------
__global__ void init_ktab() {
    int idx = blockIdx.x * 256 + threadIdx.x;
    if (idx >= NBLK) return;
    int a = 0;
    while ((a + 1) * 127 - (a + 1) * a / 2 <= idx) a++;
    int b = idx - (a * 127 - a * (a - 1) / 2) + a + 1;
    KTab[idx] = make_uchar2((unsigned char)a, (unsigned char)b);
}

// ------------------------- K0b: per-round packed-triangle offsets -----------
__global__ void init_idxtab() {
    int gid = blockIdx.x * 256 + threadIdx.x;       // over 255*NBLK
    if (gid >= 255 * NBLK) return;
    int r = gid / NBLK, idx = gid - r * NBLK;
    uchar2 kk = KTab[idx];
    int pa, qa, pb, qb;
    get_pair(r, kk.x, pa, qa);
    get_pair(r, kk.y, pb, qb);
    ushort4 v;
    v.x = (unsigned short)pidx(pa, pb);
    v.y = (unsigned short)pidx(pa, qb);
    v.z = (unsigned short)pidx(qa, pb);
    v.w = (unsigned short)pidx(qa, qb);
    IdxTab[gid] = v;
}

// ------------------------- K1: 2x2 average pool -----------------------------
__global__ void pool_kernel(const float* __restrict__ x) {
    size_t idx = (size_t)blockIdx.x * 256 + threadIdx.x;   // B*CIN*NPOS
    if (idx >= (size_t)B_SZ * CIN * NPOS) return;
    int p = (int)(idx % NPOS);
    size_t bc = idx / NPOS;
    int py = p / 17, px = p % 17;
    const float* base = x + bc * (34 * 34) + (py * 2) * 34 + px * 2;
    float2 r0 = *(const float2*)base;
    float2 r1 = *(const float2*)(base + 34);
    P_buf[idx] = (r0.x + r0.y + r1.x + r1.y) * 0.25f;
}

// ------------------------- K2: channel reduce GEMM --------------------------
// G[b][d][p] = sum_c W_red[d][c] * P[b][c][p]   (M=256, N=289, K=2048)
#define RK 16
__global__ void reduce_gemm_kernel(const float* __restrict__ W_red) {
    int b  = blockIdx.z;
    int dt = blockIdx.y * 64;
    int pt = blockIdx.x * 64;
    __shared__ float Ws[RK][68];
    __shared__ float Ps[RK][68];
    int tid = threadIdx.x;            // 256
    int ty = tid >> 4, tx = tid & 15; // 4x4 micro-tile
    float acc[4][4];
#pragma unroll
    for (int i = 0; i < 4; i++)
#pragma unroll
        for (int j = 0; j < 4; j++) acc[i][j] = 0.f;

    const float* Pb = P_buf + (size_t)b * CIN * NPOS;

    for (int k0 = 0; k0 < CIN; k0 += RK) {
#pragma unroll
        for (int u = 0; u < 4; u++) {
            int idx = tid + u * 256;
            int dd = idx >> 4, kk = idx & 15;
            Ws[kk][dd] = W_red[(size_t)(dt + dd) * CIN + k0 + kk];
        }
#pragma unroll
        for (int u = 0; u < 4; u++) {
            int idx = tid + u * 256;
            int kk = idx >> 6, pp = idx & 63;
            int p = pt + pp;
            Ps[kk][pp] = (p < NPOS) ? Pb[(size_t)(k0 + kk) * NPOS + p] : 0.f;
        }
        __syncthreads();
#pragma unroll
        for (int kk = 0; kk < RK; kk++) {
            float wv[4], pv[4];
#pragma unroll
            for (int i = 0; i < 4; i++) wv[i] = Ws[kk][ty * 4 + i];
#pragma unroll
            for (int j = 0; j < 4; j++) pv[j] = Ps[kk][tx * 4 + j];
#pragma unroll
            for (int i = 0; i < 4; i++)
#pragma unroll
                for (int j = 0; j < 4; j++)
                    acc[i][j] = fmaf(wv[i], pv[j], acc[i][j]);
        }
        __syncthreads();
    }
#pragma unroll
    for (int i = 0; i < 4; i++) {
        int d = dt + ty * 4 + i;
#pragma unroll
        for (int j = 0; j < 4; j++) {
            int p = pt + tx * 4 + j;
            if (p < NPOS)
                G_buf[((size_t)b * CR + d) * NPOS + p] = acc[i][j];
        }
    }
}

// ------------------------- K3a: mean over positions + center ---------------
__global__ void mean_center_kernel() {
    int row  = blockIdx.x * 8 + (threadIdx.x >> 5);   // (b*256 + d)
    int lane = threadIdx.x & 31;
    float* g = &G_buf[(size_t)row * NPOS];
    float sum = 0.f;
    for (int p = lane; p < NPOS; p += 32) sum += g[p];
#pragma unroll
    for (int o = 16; o; o >>= 1) sum += __shfl_xor_sync(0xFFFFFFFFu, sum, o);
    float m = sum * (1.0f / NPOS);
    for (int p = lane; p < NPOS; p += 32) g[p] -= m;
}

// ------------------------- K3b: covariance (packed lower triangle) ---------
__global__ void cov_kernel() {
    int b  = blockIdx.y;
    int tp = blockIdx.x;  // lower-tri 32x32 tile pair (it >= jt), 36 total
    int it = 0;
    { int t = tp; while ((it + 1) * (it + 2) / 2 <= t) it++; (void)t; }
    int jt = tp - it * (it + 1) / 2;

    __shared__ float SI[17][34];
    __shared__ float SJ[17][34];

    const float* Gi = G_buf + ((size_t)b * CR + it * 32) * NPOS;
    const float* Gj = G_buf + ((size_t)b * CR + jt * 32) * NPOS;

    int tid = threadIdx.x;
    int ii = (tid & 15) * 2, jj = (tid >> 4) * 2;
    float a00 = 0.f, a01 = 0.f, a10 = 0.f, a11 = 0.f;

    for (int pc = 0; pc < NPOS; pc += 17) {
#pragma unroll
        for (int u = 0; u < 3; u++) {
            int idx = tid + u * 256;
            if (idx < 544) {
                int r = idx / 17, pp = idx % 17;
                SI[pp][r] = Gi[(size_t)r * NPOS + pc + pp];
                SJ[pp][r] = Gj[(size_t)r * NPOS + pc + pp];
            }
        }
        __syncthreads();
#pragma unroll
        for (int pp = 0; pp < 17; pp++) {
            float x0 = SI[pp][ii], x1 = SI[pp][ii + 1];
            float y0 = SJ[pp][jj], y1 = SJ[pp][jj + 1];
            a00 = fmaf(x0, y0, a00); a01 = fmaf(x0, y1, a01);
            a10 = fmaf(x1, y0, a10); a11 = fmaf(x1, y1, a11);
        }
        __syncthreads();
    }
    const float inv = 1.0f / (NPOS - 1);
    float* Ap = A_buf + (size_t)b * FEAT;
    int gi = it * 32 + ii, gj = jt * 32 + jj;
    if (gi     >= gj    ) Ap[gi * (gi + 1) / 2 + gj]           = a00 * inv;
    if (gi     >= gj + 1) Ap[gi * (gi + 1) / 2 + gj + 1]       = a01 * inv;
    if (gi + 1 >= gj    ) Ap[(gi + 1) * (gi + 2) / 2 + gj]     = a10 * inv;
    if (gi + 1 >= gj + 1) Ap[(gi + 1) * (gi + 2) / 2 + gj + 1] = a11 * inv;
}

// ------------------------- K4: clustered parallel cyclic Jacobi -------------
// Cluster of 4 CTAs per matrix:
//   rank 0 : packed A in smem, angles + all 32 warps on 2x2 block updates
//   rank 1 : V^T components [0,128)   for ALL 256 eigvec rows (smem 128 KB)
//   rank 2 : V^T components [128,256)
//   rank 3 : idle, parks at the final cluster barrier
#define JSMEM (FEAT * 4 + 128 * 8)   // rank0: As+csn; rankV: Vh(131072B)+csn

__global__ __launch_bounds__(1024, 1) __cluster_dims__(4, 1, 1)
void jacobi_cluster_kernel() {
    extern __shared__ float smem[];
    float*  As  = smem;                       // rank0: FEAT; rankV: Vh[256][128]
    float2* csn = (float2*)(smem + FEAT);     // 128 (c,s)

    __shared__ __align__(8) unsigned long long go_bar;   // V-CTAs: rank0 arrives
    __shared__ __align__(8) unsigned long long ack_bar;  // rank0: V-CTAs arrive (cnt=2)

    int tid  = threadIdx.x;
    int warp = tid >> 5, lane = tid & 31;
    unsigned rank;
    asm("mov.u32 %0, %%cluster_ctarank;" : "=r"(rank));
    int b = blockIdx.x >> 2;
    float2* csn_g = CSN_g + b * 128;

    unsigned go_a  = smem_u32(&go_bar);
    unsigned ack_a = smem_u32(&ack_bar);

    // barrier init + initial population
    if (tid == 0) {
        if (rank == 0) MBAR_INIT(ack_a, 2);
        if (rank == 1 || rank == 2) MBAR_INIT(go_a, 1);
    }
    if (rank == 0) {
        for (int i = tid; i < FEAT; i += 1024)
            As[i] = A_buf[(size_t)b * FEAT + i];
    } else if (rank == 1 || rank == 2) {
        int c0 = (rank == 1) ? 0 : 128;
        for (int i = tid; i < 256 * 128; i += 1024) {
            int e = i >> 7, c = i & 127;
            As[i] = ((c0 + c) == e) ? 1.f : 0.f;   // V^T = I (column slab)
        }
    }
    __syncthreads();
    CLUSTER_SYNC();   // mbarrier inits visible before any remote arrive

    if (rank == 0) {
        // =================== rank 0: A-side Jacobi ===================
        int t_round = 0;
        for (int sw = 0; sw < NSWEEPS; sw++) {
            for (int r = 0; r < 255; r++, t_round++) {
                if (t_round > 0 && tid == 0)
                    MBAR_WAIT(ack_a, (t_round - 1) & 1);  // csn consumed
                __syncthreads();

                // ---- phase 1: angles + diagonal 2x2 of each pair ----
                if (tid < 128) {
                    int p, q; get_pair(r, tid, p, q);
                    int ipp = p * (p + 1) / 2 + p;
                    int iqq = q * (q + 1) / 2 + q;
                    int ipq = q * (q + 1) / 2 + p;
                    float app = As[ipp], aqq = As[iqq], apq = As[ipq];
                    float c = 1.f, s = 0.f;
                    if (fabsf(apq) > 1e-37f) {
                        float tau = (aqq - app) / (2.f * apq);
                        float t = copysignf(1.f, tau) /
                                  (fabsf(tau) + sqrtf(fmaf(tau, tau, 1.f)));
                        c = rsqrtf(fmaf(t, t, 1.f));
                        s = t * c;
                        As[ipp] = app - t * apq;
                        As[iqq] = aqq + t * apq;
                        As[ipq] = 0.f;
                    }
                    csn[tid] = make_float2(c, s);
                    __stcg(&csn_g[tid], make_float2(c, s));  // L2-coherent
                }
                __syncthreads();   // csn stores issued before signal
                if (tid == 0) {
                    FENCE_CLUSTER();               // release (cumulative)
                    MBAR_ARRIVE_REMOTE(go_a, 1);
                    MBAR_ARRIVE_REMOTE(go_a, 2);
                }

                // ---- phase 2: 8128 off-diagonal 2x2 blocks (smem) ----
                const ushort4* itab = IdxTab + (size_t)r * NBLK;
#pragma unroll 4
                for (int idx = tid; idx < NBLK; idx += 1024) {
                    ushort4 ix = itab[idx];       // coalesced LDG.64 (L2)
                    uchar2  kk = KTab[idx];
                    float2 ca = csn[kk.x];
                    float2 cb = csn[kk.y];
                    float b00 = As[ix.x], b01 = As[ix.y];
                    float b10 = As[ix.z], b11 = As[ix.w];
                    float r00 = ca.x * b00 - ca.y * b10;
                    float r01 = ca.x * b01 - ca.y * b11;
                    float r10 = ca.y * b00 + ca.x * b10;
                    float r11 = ca.y * b01 + ca.x * b11;
                    As[ix.x] = cb.x * r00 - cb.y * r01;
                    As[ix.y] = cb.y * r00 + cb.x * r01;
                    As[ix.z] = cb.x * r10 - cb.y * r11;
                    As[ix.w] = cb.y * r10 + cb.x * r11;
                }
                __syncthreads();
            }
        }
        if (tid < 256) {
            float wv = As[tid * (tid + 1) / 2 + tid];
            WL_buf[b * 256 + tid] = logf(fmaxf(wv, EPS_CLIP));
        }
    } else if (rank == 1 || rank == 2) {
        // ============ ranks 1,2: V^T row rotation on a column slab ==========
        int t_round = 0;
        for (int sw = 0; sw < NSWEEPS; sw++) {
            for (int r = 0; r < 255; r++, t_round++) {
                if (tid == 0) MBAR_WAIT(go_a, t_round & 1);
                __syncthreads();
                if (tid == 0) FENCE_CLUSTER();     // acquire side
                __syncthreads();
                if (tid < 128) csn[tid] = __ldcg(&csn_g[tid]);
                __syncthreads();

                // 128 pairs; warp handles one pair, lanes cover 32 float4 cols
#pragma unroll
                for (int pass = 0; pass < 4; pass++) {
                    int k = warp * 4 + pass;
                    float2 cv = csn[k];
                    int p, q; get_pair(r, k, p, q);
                    float4* vp = (float4*)(As + p * 128);
                    float4* vq = (float4*)(As + q * 128);
                    float4 a = vp[lane], d = vq[lane];
                    float4 np, nq;
                    np.x = cv.x * a.x - cv.y * d.x;  nq.x = cv.y * a.x + cv.x * d.x;
                    np.y = cv.x * a.y - cv.y * d.y;  nq.y = cv.y * a.y + cv.x * d.y;
                    np.z = cv.x * a.z - cv.y * d.z;  nq.z = cv.y * a.z + cv.x * d.z;
                    np.w = cv.x * a.w - cv.y * d.w;  nq.w = cv.y * a.w + cv.x * d.w;
                    vp[lane] = np; vq[lane] = nq;
                }
                __syncthreads();
                if (tid == 0) {
                    FENCE_CLUSTER();
                    MBAR_ARRIVE_REMOTE(ack_a, 0);
                }
            }
        }
        // write column slab back: V_buf[b][e][c0+c] = Vh[e][c]
        int c0 = (rank == 1) ? 0 : 128;
        for (int i = tid; i < 256 * 128; i += 1024) {
            int e = i >> 7, c = i & 127;
            V_buf[((size_t)b * CR + e) * CR + c0 + c] = As[i];
        }
    }
    // rank 3 falls through directly; ALL ranks park here before exit
    CLUSTER_SYNC();
}

// ------------------------- K5: logm reconstruct + triu flatten --------------
// F[b][t(i,j)] = scale(i,j) * sum_e wl[e] * V[e][i] * V[e][j]   (i <= j)
__global__ void recon_kernel() {
    int b  = blockIdx.y;
    int tp = blockIdx.x;  // upper-tri tile pairs ti <= tj among 8 -> 36
    int ti = 0;
    { int rem = tp; while (rem >= 8 - ti) { rem -= (8 - ti); ti++; } tp = rem; }
    int tj = ti + tp;

    __shared__ float SI[32][33];
    __shared__ float SJ[32][33];

    const float* Vb = V_buf + (size_t)b * CR * CR;
    const float* wl = WL_buf + b * 256;
    int tid = threadIdx.x;
    int ii = (tid & 15) * 2, jj = (tid >> 4) * 2;
    float a00 = 0.f, a01 = 0.f, a10 = 0.f, a11 = 0.f;

    for (int ec = 0; ec < 256; ec += 32) {
#pragma unroll
        for (int u = 0; u < 4; u++) {
            int idx = tid + u * 256;
            int ee = idx >> 5, c = idx & 31;
            float wv = wl[ec + ee];
            SI[ee][c] = Vb[(size_t)(ec + ee) * CR + ti * 32 + c];
            SJ[ee][c] = wv * Vb[(size_t)(ec + ee) * CR + tj * 32 + c];
        }
        __syncthreads();
#pragma unroll
        for (int ee = 0; ee < 32; ee++) {
            float x0 = SI[ee][ii], x1 = SI[ee][ii + 1];
            float y0 = SJ[ee][jj], y1 = SJ[ee][jj + 1];
            a00 = fmaf(x0, y0, a00); a01 = fmaf(x0, y1, a01);
            a10 = fmaf(x1, y0, a10); a11 = fmaf(x1, y1, a11);
        }
        __syncthreads();
    }

    float* Fb = F_buf + (size_t)b * FEAT;
    int gi = ti * 32 + ii, gj = tj * 32 + jj;
#pragma unroll
    for (int di = 0; di < 2; di++)
#pragma unroll
        for (int dj = 0; dj < 2; dj++) {
            int i = gi + di, j = gj + dj;
            if (i <= j) {
                float v = (di == 0) ? (dj == 0 ? a00 : a01)
                                    : (dj == 0 ? a10 : a11);
                int t = i * 256 - i * (i - 1) / 2 + (j - i);
                Fb[t] = v * (i == j ? 1.f : SQRT2F);
            }
        }
}

// ------------------------- K6: MLP layer 1 (float4) -------------------------
__global__ void mlp1_kernel(const float* __restrict__ W1,
                            const float* __restrict__ b1) {
    int k  = blockIdx.x;          // 0..255
    int bg = blockIdx.y * 8;      // batch group of 8
    int tid = threadIdx.x;        // 256
    const float4* wrow = (const float4*)(W1 + (size_t)k * FEAT);
    const int F4 = FEAT / 4;      // 8224
    float acc[8];
#pragma unroll
    for (int u = 0; u < 8; u++) acc[u] = 0.f;

    for (int t = tid; t < F4; t += 256) {
        float4 w = wrow[t];
#pragma unroll
        for (int u = 0; u < 8; u++) {
            float4 f = ((const float4*)(F_buf + (size_t)(bg + u) * FEAT))[t];
            acc[u] = fmaf(w.x, f.x, fmaf(w.y, f.y,
                     fmaf(w.z, f.z, fmaf(w.w, f.w, acc[u]))));
        }
    }
#pragma unroll
    for (int u = 0; u < 8; u++)
#pragma unroll
        for (int o = 16; o; o >>= 1)
            acc[u] += __shfl_xor_sync(0xFFFFFFFFu, acc[u], o);

    __shared__ float part[8][8];
    if ((tid & 31) == 0) {
#pragma unroll
        for (int u = 0; u < 8; u++) part[u][tid >> 5] = acc[u];
    }
    __syncthreads();
    if (tid < 8) {
        float s = 0.f;
#pragma unroll
        for (int w = 0; w < 8; w++) s += part[tid][w];
        s += b1[k];
        H_buf[(bg + tid) * 256 + k] = fmaxf(s, 0.f);
    }
}

// ------------------------- K7: MLP layer 2 ----------------------------------
__global__ void mlp2_kernel(const float* __restrict__ W2,
                            const float* __restrict__ b2,
                            float* __restrict__ out) {
    int b = blockIdx.x;
    int warp = threadIdx.x >> 5, lane = threadIdx.x & 31;
    if (warp < 3) {
        float s = 0.f;
        for (int k = lane; k < 256; k += 32)
            s = fmaf(H_buf[b * 256 + k], W2[warp * 256 + k], s);
#pragma unroll
        for (int o = 16; o; o >>= 1) s += __shfl_xor_sync(0xFFFFFFFFu, s, o);
        if (lane == 0) out[b * 3 + warp] = s + b2[warp];
    }
}

// ------------------------- launcher -----------------------------------------
extern "C" void kernel_launch(void* const* d_in, const int* in_sizes, int n_in,
                              void* d_out, int out_size) {
    const float* x     = (const float*)d_in[0];
    const float* W_red = (const float*)d_in[1];
    const float* W1    = (const float*)d_in[2];
    const float* b1    = (const float*)d_in[3];
    const float* W2    = (const float*)d_in[4];
    const float* b2    = (const float*)d_in[5];
    float* out = (float*)d_out;

    cudaFuncSetAttribute(jacobi_cluster_kernel,
                         cudaFuncAttributeMaxDynamicSharedMemorySize, JSMEM);

    init_ktab<<<(NBLK + 255) / 256, 256>>>();
    init_idxtab<<<(255 * NBLK + 255) / 256, 256>>>();
    pool_kernel<<<(B_SZ * CIN * NPOS) / 256, 256>>>(x);
    reduce_gemm_kernel<<<dim3(5, 4, B_SZ), 256>>>(W_red);
    mean_center_kernel<<<(B_SZ * CR) / 8, 256>>>();
    cov_kernel<<<dim3(36, B_SZ), 256>>>();
    jacobi_cluster_kernel<<<B_SZ * 4, 1024, JSMEM>>>();
    recon_kernel<<<dim3(36, B_SZ), 256>>>();
    mlp1_kernel<<<dim3(256, 4), 256>>>(W1, b1);
    mlp2_kernel<<<B_SZ, 128>>>(W2, b2, out);
}

// round 16
// speedup vs baseline: 1.5120x; 1.0782x over previous
#include <cuda_runtime.h>
#include <math.h>

#define B_SZ   32
#define CIN    2048
#define CR     256
#define NPOS   289            // 17*17
#define FEAT   32896          // 256*257/2
#define NSWEEPS 9
#define NPAIRS 128
#define NBLK   8128           // 128*127/2
#define EPS_CLIP 1e-4f
#define SQRT2F  1.41421356237309515f
#define ASIZE  41088          // padded triangle capacity (worst case 40801)

// ------------------------- device scratch (static, no alloc) ---------------
__device__ float P_buf[(size_t)B_SZ * CIN * NPOS];   // pooled   [b][c][p]
__device__ float G_buf[(size_t)B_SZ * CR * NPOS];    // reduced  [b][d][p]
__device__ float A_buf[(size_t)B_SZ * FEAT];         // packed lower-tri cov
__device__ float V_buf[(size_t)B_SZ * CR * CR];      // V^T: [b][eigvec e][comp]
__device__ float WL_buf[B_SZ * CR];                  // log(clamped eigenvalues)
__device__ float F_buf[(size_t)B_SZ * FEAT];         // flattened logm features
__device__ float H_buf[B_SZ * 256];                  // hidden layer
__device__ float2 CSN_g[B_SZ * 128];                 // per-round angles (L2)

// bank-skewed row starts: RS_g[m] = m(m+1)/2 + pad, RS_g[m] % 32 == (17*m)%32
__device__ int RS_g[256];

// precomputed Jacobi index tables (round- and sweep-invariant), natural order:
// consecutive entries share ka (broadcast csn loads) with ascending kb.
// Addresses are in the PADDED smem layout.
__device__ ushort4 IdxTab[255 * NBLK];               // 16.6 MB, L2-resident
__device__ uchar2  KTab[NBLK];                       // (ka,kb) per block

// ------------------------- helpers -----------------------------------------
// round-robin tournament pairing: round r in [0,255), pair k in [0,128)
__device__ __forceinline__ void get_pair(int r, int k, int& p, int& q) {
    if (k == 0) { p = r; q = 255; return; }
    int a = r + k;  if (a >= 255) a -= 255;
    int b = r - k;  if (b < 0)    b += 255;
    p = a < b ? a : b;
    q = a < b ? b : a;
}

__device__ __forceinline__ int pidx_pad(int i, int j) {
    int mx = i > j ? i : j;
    int mn = i > j ? j : i;
    return RS_g[mx] + mn;
}

__device__ __forceinline__ unsigned smem_u32(const void* p) {
    return (unsigned)__cvta_generic_to_shared(p);
}

#define MBAR_INIT(addr, cnt) \
    asm volatile("mbarrier.init.shared.b64 [%0], %1;" :: "r"(addr), "r"(cnt) : "memory")

// example-verified remote arrive: mapa + plain shared::cluster arrive
#define MBAR_ARRIVE_REMOTE(addr, rank) \
    asm volatile("{\n\t.reg .b32 ra;\n\t" \
                 "mapa.shared::cluster.u32 ra, %0, %1;\n\t" \
                 "mbarrier.arrive.shared::cluster.b64 _, [ra];\n\t}" \
                 :: "r"(addr), "r"(rank) : "memory")

// example-verified wait: acquire.cta try_wait spin
#define MBAR_WAIT(addr, parity) do {                                          \
    unsigned _m = (addr), _p = (parity);                                      \
    asm volatile(                                                             \
        "{\n\t.reg .pred P1;\n\t"                                             \
        "WL_%=:\n\t"                                                          \
        "mbarrier.try_wait.parity.acquire.cta.shared::cta.b64 P1, [%0], %1, 0x989680;\n\t" \
        "@P1 bra.uni WD_%=;\n\t"                                              \
        "bra.uni WL_%=;\n\t"                                                  \
        "WD_%=:\n\t}"                                                         \
        :: "r"(_m), "r"(_p) : "memory");                                      \
} while (0)

#define FENCE_CLUSTER() asm volatile("fence.acq_rel.cluster;" ::: "memory")
#define CLUSTER_SYNC() do {                                            \
    asm volatile("barrier.cluster.arrive.aligned;" ::: "memory");      \
    asm volatile("barrier.cluster.wait.aligned;"   ::: "memory");      \
} while (0)

// ------------------------- K0a: skewed row-start table ----------------------
__global__ void init_rs() {            // single thread, one-time
    int g = 0;
    for (int m = 0; m < 256; m++) {
        int T = m * (m + 1) / 2;
        int target = (17 * m - T) & 31;
        g += (target - (g & 31)) & 31;  // monotone, fixes (T+g)%32 == 17m%32
        RS_g[m] = T + g;
    }
}

// ------------------------- K0b: (ka<kb) enumeration -------------------------
__global__ void init_ktab() {
    int idx = blockIdx.x * 256 + threadIdx.x;
    if (idx >= NBLK) return;
    int a = 0;
    while ((a + 1) * 127 - (a + 1) * a / 2 <= idx) a++;
    int b = idx - (a * 127 - a * (a - 1) / 2) + a + 1;
    KTab[idx] = make_uchar2((unsigned char)a, (unsigned char)b);
}

// ------------------------- K0c: per-round padded offsets --------------------
__global__ void init_idxtab() {
    int gid = blockIdx.x * 256 + threadIdx.x;       // over 255*NBLK
    if (gid >= 255 * NBLK) return;
    int r = gid / NBLK, idx = gid - r * NBLK;
    uchar2 kk = KTab[idx];
    int pa, qa, pb, qb;
    get_pair(r, kk.x, pa, qa);
    get_pair(r, kk.y, pb, qb);
    ushort4 v;
    v.x = (unsigned short)pidx_pad(pa, pb);
    v.y = (unsigned short)pidx_pad(pa, qb);
    v.z = (unsigned short)pidx_pad(qa, pb);
    v.w = (unsigned short)pidx_pad(qa, qb);
    IdxTab[gid] = v;
}

// ------------------------- K1: 2x2 average pool -----------------------------
__global__ void pool_kernel(const float* __restrict__ x) {
    size_t idx = (size_t)blockIdx.x * 256 + threadIdx.x;   // B*CIN*NPOS
    if (idx >= (size_t)B_SZ * CIN * NPOS) return;
    int p = (int)(idx % NPOS);
    size_t bc = idx / NPOS;
    int py = p / 17, px = p % 17;
    const float* base = x + bc * (34 * 34) + (py * 2) * 34 + px * 2;
    float2 r0 = *(const float2*)base;
    float2 r1 = *(const float2*)(base + 34);
    P_buf[idx] = (r0.x + r0.y + r1.x + r1.y) * 0.25f;
}

// ------------------------- K2: channel reduce GEMM --------------------------
// G[b][d][p] = sum_c W_red[d][c] * P[b][c][p]   (M=256, N=289, K=2048)
#define RK 16
__global__ void reduce_gemm_kernel(const float* __restrict__ W_red) {
    int b  = blockIdx.z;
    int dt = blockIdx.y * 64;
    int pt = blockIdx.x * 64;
    __shared__ float Ws[RK][68];
    __shared__ float Ps[RK][68];
    int tid = threadIdx.x;            // 256
    int ty = tid >> 4, tx = tid & 15; // 4x4 micro-tile
    float acc[4][4];
#pragma unroll
    for (int i = 0; i < 4; i++)
#pragma unroll
        for (int j = 0; j < 4; j++) acc[i][j] = 0.f;

    const float* Pb = P_buf + (size_t)b * CIN * NPOS;

    for (int k0 = 0; k0 < CIN; k0 += RK) {
#pragma unroll
        for (int u = 0; u < 4; u++) {
            int idx = tid + u * 256;
            int dd = idx >> 4, kk = idx & 15;
            Ws[kk][dd] = W_red[(size_t)(dt + dd) * CIN + k0 + kk];
        }
#pragma unroll
        for (int u = 0; u < 4; u++) {
            int idx = tid + u * 256;
            int kk = idx >> 6, pp = idx & 63;
            int p = pt + pp;
            Ps[kk][pp] = (p < NPOS) ? Pb[(size_t)(k0 + kk) * NPOS + p] : 0.f;
        }
        __syncthreads();
#pragma unroll
        for (int kk = 0; kk < RK; kk++) {
            float wv[4], pv[4];
#pragma unroll
            for (int i = 0; i < 4; i++) wv[i] = Ws[kk][ty * 4 + i];
#pragma unroll
            for (int j = 0; j < 4; j++) pv[j] = Ps[kk][tx * 4 + j];
#pragma unroll
            for (int i = 0; i < 4; i++)
#pragma unroll
                for (int j = 0; j < 4; j++)
                    acc[i][j] = fmaf(wv[i], pv[j], acc[i][j]);
        }
        __syncthreads();
    }
#pragma unroll
    for (int i = 0; i < 4; i++) {
        int d = dt + ty * 4 + i;
#pragma unroll
        for (int j = 0; j < 4; j++) {
            int p = pt + tx * 4 + j;
            if (p < NPOS)
                G_buf[((size_t)b * CR + d) * NPOS + p] = acc[i][j];
        }
    }
}

// ------------------------- K3a: mean over positions + center ---------------
__global__ void mean_center_kernel() {
    int row  = blockIdx.x * 8 + (threadIdx.x >> 5);   // (b*256 + d)
    int lane = threadIdx.x & 31;
    float* g = &G_buf[(size_t)row * NPOS];
    float sum = 0.f;
    for (int p = lane; p < NPOS; p += 32) sum += g[p];
#pragma unroll
    for (int o = 16; o; o >>= 1) sum += __shfl_xor_sync(0xFFFFFFFFu, sum, o);
    float m = sum * (1.0f / NPOS);
    for (int p = lane; p < NPOS; p += 32) g[p] -= m;
}

// ------------------------- K3b: covariance (packed lower triangle) ---------
__global__ void cov_kernel() {
    int b  = blockIdx.y;
    int tp = blockIdx.x;  // lower-tri 32x32 tile pair (it >= jt), 36 total
    int it = 0;
    { int t = tp; while ((it + 1) * (it + 2) / 2 <= t) it++; (void)t; }
    int jt = tp - it * (it + 1) / 2;

    __shared__ float SI[17][34];
    __shared__ float SJ[17][34];

    const float* Gi = G_buf + ((size_t)b * CR + it * 32) * NPOS;
    const float* Gj = G_buf + ((size_t)b * CR + jt * 32) * NPOS;

    int tid = threadIdx.x;
    int ii = (tid & 15) * 2, jj = (tid >> 4) * 2;
    float a00 = 0.f, a01 = 0.f, a10 = 0.f, a11 = 0.f;

    for (int pc = 0; pc < NPOS; pc += 17) {
#pragma unroll
        for (int u = 0; u < 3; u++) {
            int idx = tid + u * 256;
            if (idx < 544) {
                int r = idx / 17, pp = idx % 17;
                SI[pp][r] = Gi[(size_t)r * NPOS + pc + pp];
                SJ[pp][r] = Gj[(size_t)r * NPOS + pc + pp];
            }
        }
        __syncthreads();
#pragma unroll
        for (int pp = 0; pp < 17; pp++) {
            float x0 = SI[pp][ii], x1 = SI[pp][ii + 1];
            float y0 = SJ[pp][jj], y1 = SJ[pp][jj + 1];
            a00 = fmaf(x0, y0, a00); a01 = fmaf(x0, y1, a01);
            a10 = fmaf(x1, y0, a10); a11 = fmaf(x1, y1, a11);
        }
        __syncthreads();
    }
    const float inv = 1.0f / (NPOS - 1);
    float* Ap = A_buf + (size_t)b * FEAT;
    int gi = it * 32 + ii, gj = jt * 32 + jj;
    if (gi     >= gj    ) Ap[gi * (gi + 1) / 2 + gj]           = a00 * inv;
    if (gi     >= gj + 1) Ap[gi * (gi + 1) / 2 + gj + 1]       = a01 * inv;
    if (gi + 1 >= gj    ) Ap[(gi + 1) * (gi + 2) / 2 + gj]     = a10 * inv;
    if (gi + 1 >= gj + 1) Ap[(gi + 1) * (gi + 2) / 2 + gj + 1] = a11 * inv;
}

// ------------------------- K4: clustered parallel cyclic Jacobi -------------
// Cluster of 4 CTAs per matrix:
//   rank 0 : PADDED packed A in smem (bank-skewed rows), angles + all 32
//            warps on 2x2 block updates
//   rank 1 : V^T components [0,128)   for ALL 256 eigvec rows (smem 128 KB)
//   rank 2 : V^T components [128,256)
//   rank 3 : idle, parks at the final cluster barrier
#define JSMEM (ASIZE * 4 + 128 * 8 + 256 * 4)   // As + csn + rss

__global__ __launch_bounds__(1024, 1) __cluster_dims__(4, 1, 1)
void jacobi_cluster_kernel() {
    extern __shared__ float smem[];
    float*  As   = smem;                        // rank0: ASIZE; rankV: Vh[256][128]
    float2* csn0 = (float2*)(smem + ASIZE);     // rank0 angles
    int*    rss  = (int*)(csn0 + 128);          // rank0 row starts
    float2* csnv = (float2*)(smem + 256 * 128); // rankV angle scratch

    __shared__ __align__(8) unsigned long long go_bar;   // V-CTAs: rank0 arrives
    __shared__ __align__(8) unsigned long long ack_bar;  // rank0: V-CTAs arrive (cnt=2)

    int tid  = threadIdx.x;
    int warp = tid >> 5, lane = tid & 31;
    unsigned rank;
    asm("mov.u32 %0, %%cluster_ctarank;" : "=r"(rank));
    int b = blockIdx.x >> 2;
    float2* csn_g = CSN_g + b * 128;

    unsigned go_a  = smem_u32(&go_bar);
    unsigned ack_a = smem_u32(&ack_bar);

    // barrier init + initial population
    if (tid == 0) {
        if (rank == 0) MBAR_INIT(ack_a, 2);
        if (rank == 1 || rank == 2) MBAR_INIT(go_a, 1);
    }
    if (rank == 0) {
        if (tid < 256) rss[tid] = RS_g[tid];
        __syncthreads();
        const float* Ab = A_buf + (size_t)b * FEAT;
        for (int i = tid; i < 256 * 256; i += 1024) {
            int row = i >> 8, col = i & 255;
            if (col <= row)
                As[rss[row] + col] = Ab[row * (row + 1) / 2 + col];
        }
    } else if (rank == 1 || rank == 2) {
        int c0 = (rank == 1) ? 0 : 128;
        for (int i = tid; i < 256 * 128; i += 1024) {
            int e = i >> 7, c = i & 127;
            As[i] = ((c0 + c) == e) ? 1.f : 0.f;   // V^T = I (column slab)
        }
    }
    __syncthreads();
    CLUSTER_SYNC();   // mbarrier inits visible before any remote arrive

    if (rank == 0) {
        // =================== rank 0: A-side Jacobi ===================
        int t_round = 0;
        for (int sw = 0; sw < NSWEEPS; sw++) {
            for (int r = 0; r < 255; r++, t_round++) {
                if (t_round > 0 && tid == 0)
                    MBAR_WAIT(ack_a, (t_round - 1) & 1);  // csn consumed
                __syncthreads();

                // ---- phase 1: angles + diagonal 2x2 of each pair ----
                if (tid < 128) {
                    int p, q; get_pair(r, tid, p, q);
                    int rp = rss[p], rq = rss[q];
                    int ipp = rp + p;
                    int iqq = rq + q;
                    int ipq = rq + p;
                    float app = As[ipp], aqq = As[iqq], apq = As[ipq];
                    float c = 1.f, s = 0.f;
                    if (fabsf(apq) > 1e-37f) {
                        float tau = (aqq - app) / (2.f * apq);
                        float t = copysignf(1.f, tau) /
                                  (fabsf(tau) + sqrtf(fmaf(tau, tau, 1.f)));
                        c = rsqrtf(fmaf(t, t, 1.f));
                        s = t * c;
                        As[ipp] = app - t * apq;
                        As[iqq] = aqq + t * apq;
                        As[ipq] = 0.f;
                    }
                    csn0[tid] = make_float2(c, s);
                    __stcg(&csn_g[tid], make_float2(c, s));  // L2-coherent
                }
                __syncthreads();   // csn stores issued before signal
                if (tid == 0) {
                    FENCE_CLUSTER();               // release (cumulative)
                    MBAR_ARRIVE_REMOTE(go_a, 1);
                    MBAR_ARRIVE_REMOTE(go_a, 2);
                }

                // ---- phase 2: 8128 off-diagonal 2x2 blocks (smem) ----
                const ushort4* itab = IdxTab + (size_t)r * NBLK;
#pragma unroll 4
                for (int idx = tid; idx < NBLK; idx += 1024) {
                    ushort4 ix = itab[idx];       // coalesced LDG.64 (L2)
                    uchar2  kk = KTab[idx];
                    float2 ca = csn0[kk.x];
                    float2 cb = csn0[kk.y];
                    float b00 = As[ix.x], b01 = As[ix.y];
                    float b10 = As[ix.z], b11 = As[ix.w];
                    float r00 = ca.x * b00 - ca.y * b10;
                    float r01 = ca.x * b01 - ca.y * b11;
                    float r10 = ca.y * b00 + ca.x * b10;
                    float r11 = ca.y * b01 + ca.x * b11;
                    As[ix.x] = cb.x * r00 - cb.y * r01;
                    As[ix.y] = cb.y * r00 + cb.x * r01;
                    As[ix.z] = cb.x * r10 - cb.y * r11;
                    As[ix.w] = cb.y * r10 + cb.x * r11;
                }
                __syncthreads();
            }
        }
        if (tid < 256) {
            float wv = As[rss[tid] + tid];
            WL_buf[b * 256 + tid] = logf(fmaxf(wv, EPS_CLIP));
        }
    } else if (rank == 1 || rank == 2) {
        // ============ ranks 1,2: V^T row rotation on a column slab ==========
        int t_round = 0;
        for (int sw = 0; sw < NSWEEPS; sw++) {
            for (int r = 0; r < 255; r++, t_round++) {
                if (tid == 0) MBAR_WAIT(go_a, t_round & 1);
                __syncthreads();
                if (tid == 0) FENCE_CLUSTER();     // acquire side
                __syncthreads();
                if (tid < 128) csnv[tid] = __ldcg(&csn_g[tid]);
                __syncthreads();

                // 128 pairs; warp handles one pair, lanes cover 32 float4 cols
#pragma unroll
                for (int pass = 0; pass < 4; pass++) {
                    int k = warp * 4 + pass;
                    float2 cv = csnv[k];
                    int p, q; get_pair(r, k, p, q);
                    float4* vp = (float4*)(As + p * 128);
                    float4* vq = (float4*)(As + q * 128);
                    float4 a = vp[lane], d = vq[lane];
                    float4 np, nq;
                    np.x = cv.x * a.x - cv.y * d.x;  nq.x = cv.y * a.x + cv.x * d.x;
                    np.y = cv.x * a.y - cv.y * d.y;  nq.y = cv.y * a.y + cv.x * d.y;
                    np.z = cv.x * a.z - cv.y * d.z;  nq.z = cv.y * a.z + cv.x * d.z;
                    np.w = cv.x * a.w - cv.y * d.w;  nq.w = cv.y * a.w + cv.x * d.w;
                    vp[lane] = np; vq[lane] = nq;
                }
                __syncthreads();
                if (tid == 0) {
                    FENCE_CLUSTER();
                    MBAR_ARRIVE_REMOTE(ack_a, 0);
                }
            }
        }
        // write column slab back: V_buf[b][e][c0+c] = Vh[e][c]
        int c0 = (rank == 1) ? 0 : 128;
        for (int i = tid; i < 256 * 128; i += 1024) {
            int e = i >> 7, c = i & 127;
            V_buf[((size_t)b * CR + e) * CR + c0 + c] = As[i];
        }
    }
    // rank 3 falls through directly; ALL ranks park here before exit
    CLUSTER_SYNC();
}

// ------------------------- K5: logm reconstruct + triu flatten --------------
// F[b][t(i,j)] = scale(i,j) * sum_e wl[e] * V[e][i] * V[e][j]   (i <= j)
__global__ void recon_kernel() {
    int b  = blockIdx.y;
    int tp = blockIdx.x;  // upper-tri tile pairs ti <= tj among 8 -> 36
    int ti = 0;
    { int rem = tp; while (rem >= 8 - ti) { rem -= (8 - ti); ti++; } tp = rem; }
    int tj = ti + tp;

    __shared__ float SI[32][33];
    __shared__ float SJ[32][33];

    const float* Vb = V_buf + (size_t)b * CR * CR;
    const float* wl = WL_buf + b * 256;
    int tid = threadIdx.x;
    int ii = (tid & 15) * 2, jj = (tid >> 4) * 2;
    float a00 = 0.f, a01 = 0.f, a10 = 0.f, a11 = 0.f;

    for (int ec = 0; ec < 256; ec += 32) {
#pragma unroll
        for (int u = 0; u < 4; u++) {
            int idx = tid + u * 256;
            int ee = idx >> 5, c = idx & 31;
            float wv = wl[ec + ee];
            SI[ee][c] = Vb[(size_t)(ec + ee) * CR + ti * 32 + c];
            SJ[ee][c] = wv * Vb[(size_t)(ec + ee) * CR + tj * 32 + c];
        }
        __syncthreads();
#pragma unroll
        for (int ee = 0; ee < 32; ee++) {
            float x0 = SI[ee][ii], x1 = SI[ee][ii + 1];
            float y0 = SJ[ee][jj], y1 = SJ[ee][jj + 1];
            a00 = fmaf(x0, y0, a00); a01 = fmaf(x0, y1, a01);
            a10 = fmaf(x1, y0, a10); a11 = fmaf(x1, y1, a11);
        }
        __syncthreads();
    }

    float* Fb = F_buf + (size_t)b * FEAT;
    int gi = ti * 32 + ii, gj = tj * 32 + jj;
#pragma unroll
    for (int di = 0; di < 2; di++)
#pragma unroll
        for (int dj = 0; dj < 2; dj++) {
            int i = gi + di, j = gj + dj;
            if (i <= j) {
                float v = (di == 0) ? (dj == 0 ? a00 : a01)
                                    : (dj == 0 ? a10 : a11);
                int t = i * 256 - i * (i - 1) / 2 + (j - i);
                Fb[t] = v * (i == j ? 1.f : SQRT2F);
            }
        }
}

// ------------------------- K6: MLP layer 1 (float4) -------------------------
__global__ void mlp1_kernel(const float* __restrict__ W1,
                            const float* __restrict__ b1) {
    int k  = blockIdx.x;          // 0..255
    int bg = blockIdx.y * 8;      // batch group of 8
    int tid = threadIdx.x;        // 256
    const float4* wrow = (const float4*)(W1 + (size_t)k * FEAT);
    const int F4 = FEAT / 4;      // 8224
    float acc[8];
#pragma unroll
    for (int u = 0; u < 8; u++) acc[u] = 0.f;

    for (int t = tid; t < F4; t += 256) {
        float4 w = wrow[t];
#pragma unroll
        for (int u = 0; u < 8; u++) {
            float4 f = ((const float4*)(F_buf + (size_t)(bg + u) * FEAT))[t];
            acc[u] = fmaf(w.x, f.x, fmaf(w.y, f.y,
                     fmaf(w.z, f.z, fmaf(w.w, f.w, acc[u]))));
        }
    }
#pragma unroll
    for (int u = 0; u < 8; u++)
#pragma unroll
        for (int o = 16; o; o >>= 1)
            acc[u] += __shfl_xor_sync(0xFFFFFFFFu, acc[u], o);

    __shared__ float part[8][8];
    if ((tid & 31) == 0) {
#pragma unroll
        for (int u = 0; u < 8; u++) part[u][tid >> 5] = acc[u];
    }
    __syncthreads();
    if (tid < 8) {
        float s = 0.f;
#pragma unroll
        for (int w = 0; w < 8; w++) s += part[tid][w];
        s += b1[k];
        H_buf[(bg + tid) * 256 + k] = fmaxf(s, 0.f);
    }
}

// ------------------------- K7: MLP layer 2 ----------------------------------
__global__ void mlp2_kernel(const float* __restrict__ W2,
                            const float* __restrict__ b2,
                            float* __restrict__ out) {
    int b = blockIdx.x;
    int warp = threadIdx.x >> 5, lane = threadIdx.x & 31;
    if (warp < 3) {
        float s = 0.f;
        for (int k = lane; k < 256; k += 32)
            s = fmaf(H_buf[b * 256 + k], W2[warp * 256 + k], s);
#pragma unroll
        for (int o = 16; o; o >>= 1) s += __shfl_xor_sync(0xFFFFFFFFu, s, o);
        if (lane == 0) out[b * 3 + warp] = s + b2[warp];
    }
}

// ------------------------- launcher -----------------------------------------
extern "C" void kernel_launch(void* const* d_in, const int* in_sizes, int n_in,
                              void* d_out, int out_size) {
    const float* x     = (const float*)d_in[0];
    const float* W_red = (const float*)d_in[1];
    const float* W1    = (const float*)d_in[2];
    const float* b1    = (const float*)d_in[3];
    const float* W2    = (const float*)d_in[4];
    const float* b2    = (const float*)d_in[5];
    float* out = (float*)d_out;

    cudaFuncSetAttribute(jacobi_cluster_kernel,
                         cudaFuncAttributeMaxDynamicSharedMemorySize, JSMEM);

    init_rs<<<1, 1>>>();
    init_ktab<<<(NBLK + 255) / 256, 256>>>();
    init_idxtab<<<(255 * NBLK + 255) / 256, 256>>>();
    pool_kernel<<<(B_SZ * CIN * NPOS) / 256, 256>>>(x);
    reduce_gemm_kernel<<<dim3(5, 4, B_SZ), 256>>>(W_red);
    mean_center_kernel<<<(B_SZ * CR) / 8, 256>>>();
    cov_kernel<<<dim3(36, B_SZ), 256>>>();
    jacobi_cluster_kernel<<<B_SZ * 4, 1024, JSMEM>>>();
    recon_kernel<<<dim3(36, B_SZ), 256>>>();
    mlp1_kernel<<<dim3(256, 4), 256>>>(W1, b1);
    mlp2_kernel<<<B_SZ, 128>>>(W2, b2, out);
}

// round 17
// speedup vs baseline: 1.6916x; 1.1188x over previous
#include <cuda_runtime.h>
#include <math.h>

#define B_SZ   32
#define CIN    2048
#define CR     256
#define NPOS   289            // 17*17
#define FEAT   32896          // 256*257/2
#define NSWEEPS 8
#define NPAIRS 128
#define NBLK   8128           // 128*127/2 real blocks
#define NBLK2  8192           // padded with dummy blocks -> exact 8 iters/thread
#define EPS_CLIP 1e-4f
#define SQRT2F  1.41421356237309515f
#define ASIZE  41088          // padded triangle capacity (worst case 40801)
#define SCRATCH (ASIZE - 4)   // dummy-block target, never read

// ------------------------- device scratch (static, no alloc) ---------------
__device__ float P_buf[(size_t)B_SZ * CIN * NPOS];   // pooled   [b][c][p]
__device__ float G_buf[(size_t)B_SZ * CR * NPOS];    // reduced  [b][d][p]
__device__ float A_buf[(size_t)B_SZ * FEAT];         // packed lower-tri cov
__device__ float V_buf[(size_t)B_SZ * CR * CR];      // V^T: [b][eigvec e][comp]
__device__ float WL_buf[B_SZ * CR];                  // log(clamped eigenvalues)
__device__ float F_buf[(size_t)B_SZ * FEAT];         // flattened logm features
__device__ float H_buf[B_SZ * 256];                  // hidden layer
__device__ float2 CSN_g[B_SZ * 128];                 // per-round angles (L2)

// bank-skewed row starts: RS_g[m] = m(m+1)/2 + pad, RS_g[m] % 32 == (17*m)%32
__device__ int RS_g[256];

// precomputed Jacobi index tables (round- and sweep-invariant), natural order:
// consecutive entries share ka (broadcast csn loads) with ascending kb.
// Addresses are in the PADDED smem layout. Entries [NBLK,NBLK2) are dummies.
__device__ ushort4 IdxTab[255 * NBLK2];              // 16.7 MB, L2-resident
__device__ uchar2  KTab[NBLK2];                      // (ka,kb) per block

// ------------------------- helpers -----------------------------------------
// round-robin tournament pairing: round r in [0,255), pair k in [0,128)
__device__ __forceinline__ void get_pair(int r, int k, int& p, int& q) {
    if (k == 0) { p = r; q = 255; return; }
    int a = r + k;  if (a >= 255) a -= 255;
    int b = r - k;  if (b < 0)    b += 255;
    p = a < b ? a : b;
    q = a < b ? b : a;
}

__device__ __forceinline__ int pidx_pad(int i, int j) {
    int mx = i > j ? i : j;
    int mn = i > j ? j : i;
    return RS_g[mx] + mn;
}

__device__ __forceinline__ unsigned smem_u32(const void* p) {
    return (unsigned)__cvta_generic_to_shared(p);
}

#define MBAR_INIT(addr, cnt) \
    asm volatile("mbarrier.init.shared.b64 [%0], %1;" :: "r"(addr), "r"(cnt) : "memory")

// example-verified remote arrive: mapa + plain shared::cluster arrive
#define MBAR_ARRIVE_REMOTE(addr, rank) \
    asm volatile("{\n\t.reg .b32 ra;\n\t" \
                 "mapa.shared::cluster.u32 ra, %0, %1;\n\t" \
                 "mbarrier.arrive.shared::cluster.b64 _, [ra];\n\t}" \
                 :: "r"(addr), "r"(rank) : "memory")

// example-verified wait: acquire.cta try_wait spin
#define MBAR_WAIT(addr, parity) do {                                          \
    unsigned _m = (addr), _p = (parity);                                      \
    asm volatile(                                                             \
        "{\n\t.reg .pred P1;\n\t"                                             \
        "WL_%=:\n\t"                                                          \
        "mbarrier.try_wait.parity.acquire.cta.shared::cta.b64 P1, [%0], %1, 0x989680;\n\t" \
        "@P1 bra.uni WD_%=;\n\t"                                              \
        "bra.uni WL_%=;\n\t"                                                  \
        "WD_%=:\n\t}"                                                         \
        :: "r"(_m), "r"(_p) : "memory");                                      \
} while (0)

#define FENCE_CLUSTER() asm volatile("fence.acq_rel.cluster;" ::: "memory")
#define CLUSTER_SYNC() do {                                            \
    asm volatile("barrier.cluster.arrive.aligned;" ::: "memory");      \
    asm volatile("barrier.cluster.wait.aligned;"   ::: "memory");      \
} while (0)

// ------------------------- K0a: skewed row-start table ----------------------
__global__ void init_rs() {            // single thread, one-time
    int g = 0;
    for (int m = 0; m < 256; m++) {
        int T = m * (m + 1) / 2;
        int target = (17 * m - T) & 31;
        g += (target - (g & 31)) & 31;  // monotone, fixes (T+g)%32 == 17m%32
        RS_g[m] = T + g;
    }
}

// ------------------------- K0b: (ka<kb) enumeration + dummies ---------------
__global__ void init_ktab() {
    int idx = blockIdx.x * 256 + threadIdx.x;
    if (idx >= NBLK2) return;
    if (idx >= NBLK) { KTab[idx] = make_uchar2(0, 0); return; }
    int a = 0;
    while ((a + 1) * 127 - (a + 1) * a / 2 <= idx) a++;
    int b = idx - (a * 127 - a * (a - 1) / 2) + a + 1;
    KTab[idx] = make_uchar2((unsigned char)a, (unsigned char)b);
}

// ------------------------- K0c: per-round padded offsets --------------------
__global__ void init_idxtab() {
    int gid = blockIdx.x * 256 + threadIdx.x;       // over 255*NBLK2
    if (gid >= 255 * NBLK2) return;
    int r = gid / NBLK2, idx = gid - r * NBLK2;
    ushort4 v;
    if (idx >= NBLK) {
        v.x = v.y = v.z = v.w = (unsigned short)SCRATCH;   // dummy block
    } else {
        uchar2 kk = KTab[idx];
        int pa, qa, pb, qb;
        get_pair(r, kk.x, pa, qa);
        get_pair(r, kk.y, pb, qb);
        v.x = (unsigned short)pidx_pad(pa, pb);
        v.y = (unsigned short)pidx_pad(pa, qb);
        v.z = (unsigned short)pidx_pad(qa, pb);
        v.w = (unsigned short)pidx_pad(qa, qb);
    }
    IdxTab[gid] = v;
}

// ------------------------- K1: 2x2 average pool -----------------------------
__global__ void pool_kernel(const float* __restrict__ x) {
    size_t idx = (size_t)blockIdx.x * 256 + threadIdx.x;   // B*CIN*NPOS
    if (idx >= (size_t)B_SZ * CIN * NPOS) return;
    int p = (int)(idx % NPOS);
    size_t bc = idx / NPOS;
    int py = p / 17, px = p % 17;
    const float* base = x + bc * (34 * 34) + (py * 2) * 34 + px * 2;
    float2 r0 = *(const float2*)base;
    float2 r1 = *(const float2*)(base + 34);
    P_buf[idx] = (r0.x + r0.y + r1.x + r1.y) * 0.25f;
}

// ------------------------- K2: channel reduce GEMM --------------------------
// G[b][d][p] = sum_c W_red[d][c] * P[b][c][p]   (M=256, N=289, K=2048)
#define RK 32
__global__ void reduce_gemm_kernel(const float* __restrict__ W_red) {
    int b  = blockIdx.z;
    int dt = blockIdx.y * 64;
    int pt = blockIdx.x * 64;
    __shared__ float Ws[RK][68];
    __shared__ float Ps[RK][68];
    int tid = threadIdx.x;            // 256
    int ty = tid >> 4, tx = tid & 15; // 4x4 micro-tile
    float acc[4][4];
#pragma unroll
    for (int i = 0; i < 4; i++)
#pragma unroll
        for (int j = 0; j < 4; j++) acc[i][j] = 0.f;

    const float* Pb = P_buf + (size_t)b * CIN * NPOS;

    for (int k0 = 0; k0 < CIN; k0 += RK) {
#pragma unroll
        for (int u = 0; u < 8; u++) {
            int idx = tid + u * 256;
            int dd = idx >> 5, kk = idx & 31;
            Ws[kk][dd] = W_red[(size_t)(dt + dd) * CIN + k0 + kk];
        }
#pragma unroll
        for (int u = 0; u < 8; u++) {
            int idx = tid + u * 256;
            int kk = idx >> 6, pp = idx & 63;
            int p = pt + pp;
            Ps[kk][pp] = (p < NPOS) ? Pb[(size_t)(k0 + kk) * NPOS + p] : 0.f;
        }
        __syncthreads();
#pragma unroll
        for (int kk = 0; kk < RK; kk++) {
            float wv[4], pv[4];
#pragma unroll
            for (int i = 0; i < 4; i++) wv[i] = Ws[kk][ty * 4 + i];
#pragma unroll
            for (int j = 0; j < 4; j++) pv[j] = Ps[kk][tx * 4 + j];
#pragma unroll
            for (int i = 0; i < 4; i++)
#pragma unroll
                for (int j = 0; j < 4; j++)
                    acc[i][j] = fmaf(wv[i], pv[j], acc[i][j]);
        }
        __syncthreads();
    }
#pragma unroll
    for (int i = 0; i < 4; i++) {
        int d = dt + ty * 4 + i;
#pragma unroll
        for (int j = 0; j < 4; j++) {
            int p = pt + tx * 4 + j;
            if (p < NPOS)
                G_buf[((size_t)b * CR + d) * NPOS + p] = acc[i][j];
        }
    }
}

// ------------------------- K3a: mean over positions + center ---------------
__global__ void mean_center_kernel() {
    int row  = blockIdx.x * 8 + (threadIdx.x >> 5);   // (b*256 + d)
    int lane = threadIdx.x & 31;
    float* g = &G_buf[(size_t)row * NPOS];
    float sum = 0.f;
    for (int p = lane; p < NPOS; p += 32) sum += g[p];
#pragma unroll
    for (int o = 16; o; o >>= 1) sum += __shfl_xor_sync(0xFFFFFFFFu, sum, o);
    float m = sum * (1.0f / NPOS);
    for (int p = lane; p < NPOS; p += 32) g[p] -= m;
}

// ------------------------- K3b: covariance (packed lower triangle) ---------
__global__ void cov_kernel() {
    int b  = blockIdx.y;
    int tp = blockIdx.x;  // lower-tri 32x32 tile pair (it >= jt), 36 total
    int it = 0;
    { int t = tp; while ((it + 1) * (it + 2) / 2 <= t) it++; (void)t; }
    int jt = tp - it * (it + 1) / 2;

    __shared__ float SI[17][34];
    __shared__ float SJ[17][34];

    const float* Gi = G_buf + ((size_t)b * CR + it * 32) * NPOS;
    const float* Gj = G_buf + ((size_t)b * CR + jt * 32) * NPOS;

    int tid = threadIdx.x;
    int ii = (tid & 15) * 2, jj = (tid >> 4) * 2;
    float a00 = 0.f, a01 = 0.f, a10 = 0.f, a11 = 0.f;

    for (int pc = 0; pc < NPOS; pc += 17) {
#pragma unroll
        for (int u = 0; u < 3; u++) {
            int idx = tid + u * 256;
            if (idx < 544) {
                int r = idx / 17, pp = idx % 17;
                SI[pp][r] = Gi[(size_t)r * NPOS + pc + pp];
                SJ[pp][r] = Gj[(size_t)r * NPOS + pc + pp];
            }
        }
        __syncthreads();
#pragma unroll
        for (int pp = 0; pp < 17; pp++) {
            float x0 = SI[pp][ii], x1 = SI[pp][ii + 1];
            float y0 = SJ[pp][jj], y1 = SJ[pp][jj + 1];
            a00 = fmaf(x0, y0, a00); a01 = fmaf(x0, y1, a01);
            a10 = fmaf(x1, y0, a10); a11 = fmaf(x1, y1, a11);
        }
        __syncthreads();
    }
    const float inv = 1.0f / (NPOS - 1);
    float* Ap = A_buf + (size_t)b * FEAT;
    int gi = it * 32 + ii, gj = jt * 32 + jj;
    if (gi     >= gj    ) Ap[gi * (gi + 1) / 2 + gj]           = a00 * inv;
    if (gi     >= gj + 1) Ap[gi * (gi + 1) / 2 + gj + 1]       = a01 * inv;
    if (gi + 1 >= gj    ) Ap[(gi + 1) * (gi + 2) / 2 + gj]     = a10 * inv;
    if (gi + 1 >= gj + 1) Ap[(gi + 1) * (gi + 2) / 2 + gj + 1] = a11 * inv;
}

// ------------------------- K4: clustered parallel cyclic Jacobi -------------
// Cluster of 4 CTAs per matrix:
//   rank 0 : PADDED packed A in smem (bank-skewed rows), angles + all 32
//            warps on 2x2 block updates (8192 padded blocks, 8 iters exact)
//   rank 1 : V^T components [0,128)   for ALL 256 eigvec rows (smem 128 KB)
//   rank 2 : V^T components [128,256)
//   rank 3 : idle, parks at the final cluster barrier
#define JSMEM (ASIZE * 4 + 128 * 8 + 256 * 4)   // As + csn + rss

__global__ __launch_bounds__(1024, 1) __cluster_dims__(4, 1, 1)
void jacobi_cluster_kernel() {
    extern __shared__ float smem[];
    float*  As   = smem;                        // rank0: ASIZE; rankV: Vh[256][128]
    float2* csn0 = (float2*)(smem + ASIZE);     // rank0 angles
    int*    rss  = (int*)(csn0 + 128);          // rank0 row starts
    float2* csnv = (float2*)(smem + 256 * 128); // rankV angle scratch

    __shared__ __align__(8) unsigned long long go_bar;   // V-CTAs: rank0 arrives
    __shared__ __align__(8) unsigned long long ack_bar;  // rank0: V-CTAs arrive (cnt=2)

    int tid  = threadIdx.x;
    int warp = tid >> 5, lane = tid & 31;
    unsigned rank;
    asm("mov.u32 %0, %%cluster_ctarank;" : "=r"(rank));
    int b = blockIdx.x >> 2;
    float2* csn_g = CSN_g + b * 128;

    unsigned go_a  = smem_u32(&go_bar);
    unsigned ack_a = smem_u32(&ack_bar);

    // barrier init + initial population
    if (tid == 0) {
        if (rank == 0) MBAR_INIT(ack_a, 2);
        if (rank == 1 || rank == 2) MBAR_INIT(go_a, 1);
    }
    if (rank == 0) {
        if (tid < 256) rss[tid] = RS_g[tid];
        __syncthreads();
        const float* Ab = A_buf + (size_t)b * FEAT;
        for (int i = tid; i < 256 * 256; i += 1024) {
            int row = i >> 8, col = i & 255;
            if (col <= row)
                As[rss[row] + col] = Ab[row * (row + 1) / 2 + col];
        }
    } else if (rank == 1 || rank == 2) {
        int c0 = (rank == 1) ? 0 : 128;
        for (int i = tid; i < 256 * 128; i += 1024) {
            int e = i >> 7, c = i & 127;
            As[i] = ((c0 + c) == e) ? 1.f : 0.f;   // V^T = I (column slab)
        }
    }
    __syncthreads();
    CLUSTER_SYNC();   // mbarrier inits visible before any remote arrive

    if (rank == 0) {
        // =================== rank 0: A-side Jacobi ===================
        int t_round = 0;
        for (int sw = 0; sw < NSWEEPS; sw++) {
            for (int r = 0; r < 255; r++, t_round++) {
                if (t_round > 0 && tid == 0)
                    MBAR_WAIT(ack_a, (t_round - 1) & 1);  // csn consumed
                __syncthreads();

                // ---- phase 1: angles + diagonal 2x2 of each pair ----
                if (tid < 128) {
                    int p, q; get_pair(r, tid, p, q);
                    int rp = rss[p], rq = rss[q];
                    int ipp = rp + p;
                    int iqq = rq + q;
                    int ipq = rq + p;
                    float app = As[ipp], aqq = As[iqq], apq = As[ipq];
                    float c = 1.f, s = 0.f;
                    if (fabsf(apq) > 1e-37f) {
                        float tau = (aqq - app) / (2.f * apq);
                        float t = copysignf(1.f, tau) /
                                  (fabsf(tau) + sqrtf(fmaf(tau, tau, 1.f)));
                        c = rsqrtf(fmaf(t, t, 1.f));
                        s = t * c;
                        As[ipp] = app - t * apq;
                        As[iqq] = aqq + t * apq;
                        As[ipq] = 0.f;
                    }
                    csn0[tid] = make_float2(c, s);
                    __stcg(&csn_g[tid], make_float2(c, s));  // L2-coherent
                }
                __syncthreads();   // csn stores issued before signal
                if (tid == 0) {
                    FENCE_CLUSTER();               // release (cumulative)
                    MBAR_ARRIVE_REMOTE(go_a, 1);
                    MBAR_ARRIVE_REMOTE(go_a, 2);
                }

                // ---- phase 2: 8192 padded 2x2 blocks, exact 8 per thread ----
                const ushort4* itab = IdxTab + (size_t)r * NBLK2;
#pragma unroll
                for (int u = 0; u < 8; u++) {
                    int idx = tid + u * 1024;
                    ushort4 ix = itab[idx];       // coalesced LDG.64 (L2)
                    uchar2  kk = KTab[idx];
                    float2 ca = csn0[kk.x];
                    float2 cb = csn0[kk.y];
                    float b00 = As[ix.x], b01 = As[ix.y];
                    float b10 = As[ix.z], b11 = As[ix.w];
                    float r00 = ca.x * b00 - ca.y * b10;
                    float r01 = ca.x * b01 - ca.y * b11;
                    float r10 = ca.y * b00 + ca.x * b10;
                    float r11 = ca.y * b01 + ca.x * b11;
                    As[ix.x] = cb.x * r00 - cb.y * r01;
                    As[ix.y] = cb.y * r00 + cb.x * r01;
                    As[ix.z] = cb.x * r10 - cb.y * r11;
                    As[ix.w] = cb.y * r10 + cb.x * r11;
                }
                __syncthreads();
            }
        }
        if (tid < 256) {
            float wv = As[rss[tid] + tid];
            WL_buf[b * 256 + tid] = logf(fmaxf(wv, EPS_CLIP));
        }
    } else if (rank == 1 || rank == 2) {
        // ============ ranks 1,2: V^T row rotation on a column slab ==========
        int t_round = 0;
        for (int sw = 0; sw < NSWEEPS; sw++) {
            for (int r = 0; r < 255; r++, t_round++) {
                if (tid == 0) MBAR_WAIT(go_a, t_round & 1);
                __syncthreads();
                if (tid == 0) FENCE_CLUSTER();     // acquire side
                __syncthreads();
                if (tid < 128) csnv[tid] = __ldcg(&csn_g[tid]);
                __syncthreads();

                // 128 pairs; warp handles one pair, lanes cover 32 float4 cols
#pragma unroll
                for (int pass = 0; pass < 4; pass++) {
                    int k = warp * 4 + pass;
                    float2 cv = csnv[k];
                    int p, q; get_pair(r, k, p, q);
                    float4* vp = (float4*)(As + p * 128);
                    float4* vq = (float4*)(As + q * 128);
                    float4 a = vp[lane], d = vq[lane];
                    float4 np, nq;
                    np.x = cv.x * a.x - cv.y * d.x;  nq.x = cv.y * a.x + cv.x * d.x;
                    np.y = cv.x * a.y - cv.y * d.y;  nq.y = cv.y * a.y + cv.x * d.y;
                    np.z = cv.x * a.z - cv.y * d.z;  nq.z = cv.y * a.z + cv.x * d.z;
                    np.w = cv.x * a.w - cv.y * d.w;  nq.w = cv.y * a.w + cv.x * d.w;
                    vp[lane] = np; vq[lane] = nq;
                }
                __syncthreads();
                if (tid == 0) {
                    FENCE_CLUSTER();
                    MBAR_ARRIVE_REMOTE(ack_a, 0);
                }
            }
        }
        // write column slab back: V_buf[b][e][c0+c] = Vh[e][c]
        int c0 = (rank == 1) ? 0 : 128;
        for (int i = tid; i < 256 * 128; i += 1024) {
            int e = i >> 7, c = i & 127;
            V_buf[((size_t)b * CR + e) * CR + c0 + c] = As[i];
        }
    }
    // rank 3 falls through directly; ALL ranks park here before exit
    CLUSTER_SYNC();
}

// ------------------------- K5: logm reconstruct + triu flatten --------------
// F[b][t(i,j)] = scale(i,j) * sum_e wl[e] * V[e][i] * V[e][j]   (i <= j)
__global__ void recon_kernel() {
    int b  = blockIdx.y;
    int tp = blockIdx.x;  // upper-tri tile pairs ti <= tj among 8 -> 36
    int ti = 0;
    { int rem = tp; while (rem >= 8 - ti) { rem -= (8 - ti); ti++; } tp = rem; }
    int tj = ti + tp;

    __shared__ float SI[32][33];
    __shared__ float SJ[32][33];

    const float* Vb = V_buf + (size_t)b * CR * CR;
    const float* wl = WL_buf + b * 256;
    int tid = threadIdx.x;
    int ii = (tid & 15) * 2, jj = (tid >> 4) * 2;
    float a00 = 0.f, a01 = 0.f, a10 = 0.f, a11 = 0.f;

    for (int ec = 0; ec < 256; ec += 32) {
#pragma unroll
        for (int u = 0; u < 4; u++) {
            int idx = tid + u * 256;
            int ee = idx >> 5, c = idx & 31;
            float wv = wl[ec + ee];
            SI[ee][c] = Vb[(size_t)(ec + ee) * CR + ti * 32 + c];
            SJ[ee][c] = wv * Vb[(size_t)(ec + ee) * CR + tj * 32 + c];
        }
        __syncthreads();
#pragma unroll
        for (int ee = 0; ee < 32; ee++) {
            float x0 = SI[ee][ii], x1 = SI[ee][ii + 1];
            float y0 = SJ[ee][jj], y1 = SJ[ee][jj + 1];
            a00 = fmaf(x0, y0, a00); a01 = fmaf(x0, y1, a01);
            a10 = fmaf(x1, y0, a10); a11 = fmaf(x1, y1, a11);
        }
        __syncthreads();
    }

    float* Fb = F_buf + (size_t)b * FEAT;
    int gi = ti * 32 + ii, gj = tj * 32 + jj;
#pragma unroll
    for (int di = 0; di < 2; di++)
#pragma unroll
        for (int dj = 0; dj < 2; dj++) {
            int i = gi + di, j = gj + dj;
            if (i <= j) {
                float v = (di == 0) ? (dj == 0 ? a00 : a01)
                                    : (dj == 0 ? a10 : a11);
                int t = i * 256 - i * (i - 1) / 2 + (j - i);
                Fb[t] = v * (i == j ? 1.f : SQRT2F);
            }
        }
}

// ------------------------- K6: MLP layer 1 (float4) -------------------------
__global__ void mlp1_kernel(const float* __restrict__ W1,
                            const float* __restrict__ b1) {
    int k  = blockIdx.x;          // 0..255
    int bg = blockIdx.y * 8;      // batch group of 8
    int tid = threadIdx.x;        // 256
    const float4* wrow = (const float4*)(W1 + (size_t)k * FEAT);
    const int F4 = FEAT / 4;      // 8224
    float acc[8];
#pragma unroll
    for (int u = 0; u < 8; u++) acc[u] = 0.f;

    for (int t = tid; t < F4; t += 256) {
        float4 w = wrow[t];
#pragma unroll
        for (int u = 0; u < 8; u++) {
            float4 f = ((const float4*)(F_buf + (size_t)(bg + u) * FEAT))[t];
            acc[u] = fmaf(w.x, f.x, fmaf(w.y, f.y,
                     fmaf(w.z, f.z, fmaf(w.w, f.w, acc[u]))));
        }
    }
#pragma unroll
    for (int u = 0; u < 8; u++)
#pragma unroll
        for (int o = 16; o; o >>= 1)
            acc[u] += __shfl_xor_sync(0xFFFFFFFFu, acc[u], o);

    __shared__ float part[8][8];
    if ((tid & 31) == 0) {
#pragma unroll
        for (int u = 0; u < 8; u++) part[u][tid >> 5] = acc[u];
    }
    __syncthreads();
    if (tid < 8) {
        float s = 0.f;
#pragma unroll
        for (int w = 0; w < 8; w++) s += part[tid][w];
        s += b1[k];
        H_buf[(bg + tid) * 256 + k] = fmaxf(s, 0.f);
    }
}

// ------------------------- K7: MLP layer 2 ----------------------------------
__global__ void mlp2_kernel(const float* __restrict__ W2,
                            const float* __restrict__ b2,
                            float* __restrict__ out) {
    int b = blockIdx.x;
    int warp = threadIdx.x >> 5, lane = threadIdx.x & 31;
    if (warp < 3) {
        float s = 0.f;
        for (int k = lane; k < 256; k += 32)
            s = fmaf(H_buf[b * 256 + k], W2[warp * 256 + k], s);
#pragma unroll
        for (int o = 16; o; o >>= 1) s += __shfl_xor_sync(0xFFFFFFFFu, s, o);
        if (lane == 0) out[b * 3 + warp] = s + b2[warp];
    }
}

// ------------------------- launcher -----------------------------------------
extern "C" void kernel_launch(void* const* d_in, const int* in_sizes, int n_in,
                              void* d_out, int out_size) {
    const float* x     = (const float*)d_in[0];
    const float* W_red = (const float*)d_in[1];
    const float* W1    = (const float*)d_in[2];
    const float* b1    = (const float*)d_in[3];
    const float* W2    = (const float*)d_in[4];
    const float* b2    = (const float*)d_in[5];
    float* out = (float*)d_out;

    cudaFuncSetAttribute(jacobi_cluster_kernel,
                         cudaFuncAttributeMaxDynamicSharedMemorySize, JSMEM);

    init_rs<<<1, 1>>>();
    init_ktab<<<NBLK2 / 256, 256>>>();
    init_idxtab<<<(255 * NBLK2) / 256, 256>>>();
    pool_kernel<<<(B_SZ * CIN * NPOS) / 256, 256>>>(x);
    reduce_gemm_kernel<<<dim3(5, 4, B_SZ), 256>>>(W_red);
    mean_center_kernel<<<(B_SZ * CR) / 8, 256>>>();
    cov_kernel<<<dim3(36, B_SZ), 256>>>();
    jacobi_cluster_kernel<<<B_SZ * 4, 1024, JSMEM>>>();
    recon_kernel<<<dim3(36, B_SZ), 256>>>();
    mlp1_kernel<<<dim3(256, 4), 256>>>(W1, b1);
    mlp2_kernel<<<B_SZ, 128>>>(W2, b2, out);
}